// round 11
// baseline (speedup 1.0000x reference)
#include <cuda_runtime.h>
#include <math.h>

#define JW 10
#define DCH 100          // days per chunk (T=50000 -> 500 chunks)
#define MAXCH 1024

// Scratch (allocation-free rule: __device__ globals)
__device__ float g_Pex[MAXCH];   // exclusive prefix of log r at chunk starts

typedef unsigned long long u64;

// ---- packed f32x2 helpers (sm_103a) ----
__device__ __forceinline__ u64 pk2(float lo, float hi) {
    u64 r; asm("mov.b64 %0, {%1, %2};" : "=l"(r) : "f"(lo), "f"(hi)); return r;
}
__device__ __forceinline__ u64 mul2(u64 a, u64 b) {
    u64 d; asm("mul.rn.f32x2 %0, %1, %2;" : "=l"(d) : "l"(a), "l"(b)); return d;
}
__device__ __forceinline__ u64 fma2(u64 a, u64 b, u64 c) {
    u64 d; asm("fma.rn.f32x2 %0, %1, %2, %3;" : "=l"(d) : "l"(a), "l"(b), "l"(c)); return d;
}
__device__ __forceinline__ u64 add2(u64 a, u64 b) {
    u64 d; asm("add.rn.f32x2 %0, %1, %2;" : "=l"(d) : "l"(a), "l"(b)); return d;
}
// 16-byte store, default (write-back) caching: lets L2 absorb the write burst
// so the DRAM drain overlaps subsequent work instead of extending this kernel.
__device__ __forceinline__ void stwb128(u64* p, u64 lo, u64 hi) {
    asm volatile("st.global.v2.b64 [%0], {%1, %2};"
                 :: "l"(p), "l"(lo), "l"(hi) : "memory");
}

// log(1+x), |x| <= ~0.011: degree-5 poly, abs err ~1e-9
__device__ __forceinline__ float log1p_poly(float x) {
    float p = fmaf(x, 0.2f, -0.25f);
    p = fmaf(x, p, 1.0f / 3.0f);
    p = fmaf(x, p, -0.5f);
    p = fmaf(x, p, 1.0f);
    return x * p;
}

// ---- prep (single block, coalesced) — R8-proven anchor computation ----
__global__ void __launch_bounds__(1024) prep_kernel(const float* __restrict__ r,
                                                    int T, int nch) {
    // PDL: allow the dependent (main) grid to begin scheduling immediately;
    // its griddepcontrol.wait still blocks until this grid fully completes.
    asm volatile("griddepcontrol.launch_dependents;" ::: "memory");

    __shared__ float s8[6272];    // 8-day log-sums: ceil(T/8) <= 6250
    __shared__ float cs[512];     // 200-day super-chunk sums
    int t = threadIdx.x;

    int n4 = (T + 3) >> 2;        // # float4 groups (T=50000 -> 12500)
    int n8 = (T + 7) >> 3;        // # 8-day groups  (6250)

    for (int k = 0; k < (n4 + 1023) / 1024; ++k) {
        int i4 = k * 1024 + t;
        float v = 0.0f;
        if (i4 < n4) {
            int d = i4 * 4;
            if (d + 4 <= T) {
                float4 rv = *(const float4*)(r + d);   // coalesced
                v = (log1p_poly(rv.x - 1.0f) + log1p_poly(rv.y - 1.0f))
                  + (log1p_poly(rv.z - 1.0f) + log1p_poly(rv.w - 1.0f));
            } else {
                for (int i = d; i < T; ++i) v += log1p_poly(r[i] - 1.0f);
            }
        }
        float w = v + __shfl_xor_sync(0xffffffffu, v, 1);
        int i8 = i4 >> 1;
        if ((t & 1) == 0 && i4 < n4 && i8 < n8) s8[i8] = w;
    }
    __syncthreads();

    // 200-day super-chunk sums (25 x 8-day groups each)
    if (t < 512) {
        float s = 0.0f;
        int c2 = t;
        if (c2 < (nch + 1) / 2) {
            int base = c2 * 25;
            float a0 = 0.f, a1 = 0.f, a2 = 0.f, a3 = 0.f, a4 = 0.f;
#pragma unroll
            for (int i = 0; i < 25; i += 5) {
                a0 += s8[base + i];
                a1 += s8[base + i + 1];
                a2 += s8[base + i + 2];
                a3 += s8[base + i + 3];
                a4 += s8[base + i + 4];
            }
            s = ((a0 + a1) + (a2 + a3)) + a4;
        }
        cs[t] = s;
    }
    __syncthreads();

    // Hillis-Steele inclusive scan over 512 super-chunk sums
#pragma unroll
    for (int off = 1; off < 512; off <<= 1) {
        float u = 0.0f;
        if (t < 512 && t >= off) u = cs[t - off];
        __syncthreads();
        if (t < 512) cs[t] += u;
        __syncthreads();
    }
    // emit 100-day-chunk exclusive prefixes
    if (t < nch) {
        int c2 = t >> 1;
        float superExcl = (c2 == 0) ? 0.0f : cs[c2 - 1];
        if ((t & 1) == 0) {
            g_Pex[t] = superExcl;
        } else {
            // + first 100 days of super-chunk c2: 12 x 8-day + 4 days from r
            float h = 0.0f;
            int b = c2 * 25;
#pragma unroll
            for (int i = 0; i < 12; ++i) h += s8[b + i];
            int d = (c2 * 200) + 96;
            h += (log1p_poly(r[d] - 1.0f) + log1p_poly(r[d + 1] - 1.0f))
               + (log1p_poly(r[d + 2] - 1.0f) + log1p_poly(r[d + 3] - 1.0f));
            g_Pex[t] = superExcl + h;
        }
    }
}

// ---- main kernel: QS=4 samples/thread, two f32x2 windows, STG.128 (wb) ----
__global__ void __launch_bounds__(128) main_kernel(
    const float* __restrict__ r,      // (T,)
    const float* __restrict__ warm,   // (J,S)
    const float* __restrict__ Ts,     // (S,)
    const float* __restrict__ rho,    // (S,)
    const float* __restrict__ pi,     // (J,S)
    u64* __restrict__ out,            // (T, S/2) packed f32x2
    int T, int S)
{
    int q = blockIdx.x * blockDim.x + threadIdx.x;   // quad index
    int nquads = S >> 2;
    if (q >= nquads) {
        asm volatile("griddepcontrol.wait;" ::: "memory");
        return;
    }
    int c  = blockIdx.y;
    int d0 = c * DCH;

    float4 Ts4  = ((const float4*)Ts)[q];
    float4 rho4 = ((const float4*)rho)[q];
    float t0 = 1.0f / Ts4.x, t1 = 1.0f / Ts4.y;
    float t2 = 1.0f / Ts4.z, t3 = 1.0f / Ts4.w;

    u64 pirA[JW], pirB[JW];
#pragma unroll
    for (int j = 0; j < JW; ++j) {
        float4 p4 = ((const float4*)(pi + j * S))[q];
        pirA[j] = pk2(p4.x * rho4.x, p4.y * rho4.y);
        pirB[j] = pk2(p4.z * rho4.z, p4.w * rho4.w);
    }

    const u64 C1A = pk2(t0, t1), C1B = pk2(t2, t3);
    const u64 C2A = pk2(0.5f * t0 * (t0 - 1.0f), 0.5f * t1 * (t1 - 1.0f));
    const u64 C2B = pk2(0.5f * t2 * (t2 - 1.0f), 0.5f * t3 * (t3 - 1.0f));
    const u64 ONE2 = pk2(1.0f, 1.0f);

    u64 winA[JW], winB[JW];
    if (c == 0) {
#pragma unroll
        for (int j = 0; j < JW; ++j) {
            float4 w4 = ((const float4*)(warm + (JW - 1 - j) * S))[q];
            winA[j] = pk2(w4.x, w4.y);
            winB[j] = pk2(w4.z, w4.w);
        }
        asm volatile("griddepcontrol.wait;" ::: "memory");  // no prep data used
    } else {
        float4 wl4 = ((const float4*)(warm + (JW - 1) * S))[q];
        // prep-produced anchor: block until prep has completed (PDL edge)
        asm volatile("griddepcontrol.wait;" ::: "memory");
        float Pex = g_Pex[c];                 // sum log r[0..d0-1]
        winA[0] = pk2(wl4.x * __expf(Pex * t0), wl4.y * __expf(Pex * t1));
        winB[0] = pk2(wl4.z * __expf(Pex * t2), wl4.w * __expf(Pex * t3));
        // backward walk: (1+v)^(-t) ~= 1 - t v + t(t+1)/2 v^2 - t(t+1)(t+2)/6 v^3
        u64 B1A = pk2(-t0, -t1), B1B = pk2(-t2, -t3);
        u64 B2A = pk2(0.5f * t0 * (t0 + 1.0f), 0.5f * t1 * (t1 + 1.0f));
        u64 B2B = pk2(0.5f * t2 * (t2 + 1.0f), 0.5f * t3 * (t3 + 1.0f));
        u64 B3A = pk2(-t0 * (t0 + 1.0f) * (t0 + 2.0f) / 6.0f,
                      -t1 * (t1 + 1.0f) * (t1 + 2.0f) / 6.0f);
        u64 B3B = pk2(-t2 * (t2 + 1.0f) * (t2 + 2.0f) / 6.0f,
                      -t3 * (t3 + 1.0f) * (t3 + 2.0f) / 6.0f);
#pragma unroll
        for (int j = 1; j < JW; ++j) {
            float v = r[d0 - j] - 1.0f;
            u64 v2 = pk2(v, v);
            u64 eA = fma2(v2, fma2(v2, fma2(v2, B3A, B2A), B1A), ONE2);
            u64 eB = fma2(v2, fma2(v2, fma2(v2, B3B, B2B), B1B), ONE2);
            winA[j] = mul2(winA[j - 1], eA);
            winB[j] = mul2(winB[j - 1], eB);
        }
    }
    u64 aA = winA[0], aB = winB[0];

    const float4* R4 = (const float4*)(r + d0);   // d0*4B is 400B-aligned
    u64* o = out + ((size_t)d0 * nquads + q) * 2;
    const size_t ostep = (size_t)nquads * 2;

#define STEP(rv) do {                                               \
        u64 mA0 = mul2(pirA[0], winA[0]);                           \
        u64 mA1 = mul2(pirA[1], winA[1]);                           \
        u64 mB0 = mul2(pirB[0], winB[0]);                           \
        u64 mB1 = mul2(pirB[1], winB[1]);                           \
        mA0 = fma2(pirA[2], winA[2], mA0);                          \
        mA1 = fma2(pirA[3], winA[3], mA1);                          \
        mB0 = fma2(pirB[2], winB[2], mB0);                          \
        mB1 = fma2(pirB[3], winB[3], mB1);                          \
        mA0 = fma2(pirA[4], winA[4], mA0);                          \
        mA1 = fma2(pirA[5], winA[5], mA1);                          \
        mB0 = fma2(pirB[4], winB[4], mB0);                          \
        mB1 = fma2(pirB[5], winB[5], mB1);                          \
        mA0 = fma2(pirA[6], winA[6], mA0);                          \
        mA1 = fma2(pirA[7], winA[7], mA1);                          \
        mB0 = fma2(pirB[6], winB[6], mB0);                          \
        mB1 = fma2(pirB[7], winB[7], mB1);                          \
        mA0 = fma2(pirA[8], winA[8], mA0);                          \
        mA1 = fma2(pirA[9], winA[9], mA1);                          \
        mB0 = fma2(pirB[8], winB[8], mB0);                          \
        mB1 = fma2(pirB[9], winB[9], mB1);                          \
        stwb128(o, add2(mA0, mA1), add2(mB0, mB1));                 \
        o += ostep;                                                 \
        float vv = (rv) - 1.0f;                                     \
        u64 v2 = pk2(vv, vv);                                       \
        u64 eA = fma2(v2, fma2(v2, C2A, C1A), ONE2);                \
        u64 eB = fma2(v2, fma2(v2, C2B, C1B), ONE2);                \
        aA = mul2(aA, eA);                                          \
        aB = mul2(aB, eB);                                          \
        _Pragma("unroll")                                           \
        for (int j = JW - 1; j > 0; --j) {                          \
            winA[j] = winA[j - 1];                                  \
            winB[j] = winB[j - 1];                                  \
        }                                                           \
        winA[0] = aA;                                               \
        winB[0] = aB;                                               \
    } while (0)

    if (d0 + DCH <= T) {
        // 25 iters of 4 days; unroll 5 -> 20 days/body = 2 full window rotations
#pragma unroll 5
        for (int it = 0; it < DCH / 4; ++it) {
            float4 L = R4[it];
            STEP(L.x);
            STEP(L.y);
            STEP(L.z);
            STEP(L.w);
        }
    } else {
        for (int d = d0; d < T; ++d) {
            float rv = r[d];
            STEP(rv);
        }
    }
#undef STEP
}

extern "C" void kernel_launch(void* const* d_in, const int* in_sizes, int n_in,
                              void* d_out, int out_size) {
    const float* r    = (const float*)d_in[0];  // (1,T)
    const float* warm = (const float*)d_in[1];  // (J,S)
    const float* Ts   = (const float*)d_in[2];  // (S,)
    const float* rho  = (const float*)d_in[3];  // (S,)
    const float* pi   = (const float*)d_in[4];  // (J,S)

    int T = in_sizes[0];
    int S = in_sizes[2];
    int nch = (T + DCH - 1) / DCH;

    prep_kernel<<<1, 1024>>>(r, T, nch);

    int nquads = S / 4;
    dim3 grid((nquads + 127) / 128, nch);

    // PDL launch of main: may begin scheduling while prep runs; the
    // griddepcontrol.wait inside orders the g_Pex read after prep completes.
    cudaLaunchConfig_t cfg = {};
    cfg.gridDim = grid;
    cfg.blockDim = dim3(128, 1, 1);
    cfg.dynamicSmemBytes = 0;
    cfg.stream = 0;
    cudaLaunchAttribute at[1];
    at[0].id = cudaLaunchAttributeProgrammaticStreamSerialization;
    at[0].val.programmaticStreamSerializationAllowed = 1;
    cfg.attrs = at;
    cfg.numAttrs = 1;

    cudaError_t e = cudaLaunchKernelEx(&cfg, main_kernel,
                                       r, warm, Ts, rho, pi, (u64*)d_out, T, S);
    if (e != cudaSuccess) {
        // fallback: plain serial launch (identical compute path)
        main_kernel<<<grid, 128>>>(r, warm, Ts, rho, pi, (u64*)d_out, T, S);
    }
}

// round 12
// speedup vs baseline: 1.1004x; 1.1004x over previous
#include <cuda_runtime.h>
#include <math.h>

#define JW 10
#define DCH 100          // days per chunk (T=50000 -> 500 chunks)
#define MAXCH 1024
#define PKMAX 13         // prep prefetch depth: covers T <= 13*4096 = 53248

// Scratch (allocation-free rule: __device__ globals)
__device__ float g_Pex[MAXCH];   // exclusive prefix of log r at chunk starts

typedef unsigned long long u64;

// ---- packed f32x2 helpers (sm_103a) ----
__device__ __forceinline__ u64 pk2(float lo, float hi) {
    u64 r; asm("mov.b64 %0, {%1, %2};" : "=l"(r) : "f"(lo), "f"(hi)); return r;
}
__device__ __forceinline__ u64 mul2(u64 a, u64 b) {
    u64 d; asm("mul.rn.f32x2 %0, %1, %2;" : "=l"(d) : "l"(a), "l"(b)); return d;
}
__device__ __forceinline__ u64 fma2(u64 a, u64 b, u64 c) {
    u64 d; asm("fma.rn.f32x2 %0, %1, %2, %3;" : "=l"(d) : "l"(a), "l"(b), "l"(c)); return d;
}
__device__ __forceinline__ u64 add2(u64 a, u64 b) {
    u64 d; asm("add.rn.f32x2 %0, %1, %2;" : "=l"(d) : "l"(a), "l"(b)); return d;
}
// 16-byte streaming store (evict-first): proven best in R8/R10
__device__ __forceinline__ void stcs128(u64* p, u64 lo, u64 hi) {
    asm volatile("st.global.cs.v2.b64 [%0], {%1, %2};"
                 :: "l"(p), "l"(lo), "l"(hi) : "memory");
}

// log(1+x), |x| <= ~0.011: degree-5 poly, abs err ~1e-9
__device__ __forceinline__ float log1p_poly(float x) {
    float p = fmaf(x, 0.2f, -0.25f);
    p = fmaf(x, p, 1.0f / 3.0f);
    p = fmaf(x, p, -0.5f);
    p = fmaf(x, p, 1.0f);
    return x * p;
}

// ---- prep (single block, coalesced, MLP-prefetched) ----
__global__ void __launch_bounds__(1024) prep_kernel(const float* __restrict__ r,
                                                    int T, int nch) {
    // PDL: let the dependent (main) grid begin scheduling immediately.
    asm volatile("griddepcontrol.launch_dependents;" ::: "memory");

    __shared__ float s8[6272];    // 8-day log-sums: ceil(T/8) <= 6250
    __shared__ float cs[512];     // 200-day super-chunk sums
    int t = threadIdx.x;

    int n4 = (T + 3) >> 2;        // # float4 groups (T=50000 -> 12500)
    int n8 = (T + 7) >> 3;        // # 8-day groups  (6250)

    // Prefetch ALL rounds up-front (MLP ~= PKMAX) -- one DRAM latency wall.
    float4 buf[PKMAX];
#pragma unroll
    for (int k = 0; k < PKMAX; ++k) {
        int i4 = k * 1024 + t;
        buf[k] = make_float4(1.0f, 1.0f, 1.0f, 1.0f);
        if (i4 * 4 + 4 <= T) buf[k] = *(const float4*)(r + i4 * 4);
    }
#pragma unroll
    for (int k = 0; k < PKMAX; ++k) {
        int i4 = k * 1024 + t;
        float v = 0.0f;
        if (i4 < n4) {
            int d = i4 * 4;
            if (d + 4 <= T) {
                float4 rv = buf[k];
                v = (log1p_poly(rv.x - 1.0f) + log1p_poly(rv.y - 1.0f))
                  + (log1p_poly(rv.z - 1.0f) + log1p_poly(rv.w - 1.0f));
            } else {
                for (int i = d; i < T; ++i) v += log1p_poly(r[i] - 1.0f);
            }
        }
        float w = v + __shfl_xor_sync(0xffffffffu, v, 1);
        int i8 = i4 >> 1;
        if ((t & 1) == 0 && i4 < n4 && i8 < n8) s8[i8] = w;
    }
    // fallback for T beyond prefetch reach (not taken at T=50000)
    for (int k = PKMAX; k < (n4 + 1023) / 1024; ++k) {
        int i4 = k * 1024 + t;
        float v = 0.0f;
        if (i4 < n4) {
            int d = i4 * 4;
            if (d + 4 <= T) {
                float4 rv = *(const float4*)(r + d);
                v = (log1p_poly(rv.x - 1.0f) + log1p_poly(rv.y - 1.0f))
                  + (log1p_poly(rv.z - 1.0f) + log1p_poly(rv.w - 1.0f));
            } else {
                for (int i = d; i < T; ++i) v += log1p_poly(r[i] - 1.0f);
            }
        }
        float w = v + __shfl_xor_sync(0xffffffffu, v, 1);
        int i8 = i4 >> 1;
        if ((t & 1) == 0 && i4 < n4 && i8 < n8) s8[i8] = w;
    }
    __syncthreads();

    // 200-day super-chunk sums (25 x 8-day groups each)
    if (t < 512) {
        float s = 0.0f;
        int c2 = t;
        if (c2 < (nch + 1) / 2) {
            int base = c2 * 25;
            float a0 = 0.f, a1 = 0.f, a2 = 0.f, a3 = 0.f, a4 = 0.f;
#pragma unroll
            for (int i = 0; i < 25; i += 5) {
                a0 += s8[base + i];
                a1 += s8[base + i + 1];
                a2 += s8[base + i + 2];
                a3 += s8[base + i + 3];
                a4 += s8[base + i + 4];
            }
            s = ((a0 + a1) + (a2 + a3)) + a4;
        }
        cs[t] = s;
    }
    __syncthreads();

    // Hillis-Steele inclusive scan over 512 super-chunk sums
#pragma unroll
    for (int off = 1; off < 512; off <<= 1) {
        float u = 0.0f;
        if (t < 512 && t >= off) u = cs[t - off];
        __syncthreads();
        if (t < 512) cs[t] += u;
        __syncthreads();
    }
    // emit 100-day-chunk exclusive prefixes
    if (t < nch) {
        int c2 = t >> 1;
        float superExcl = (c2 == 0) ? 0.0f : cs[c2 - 1];
        if ((t & 1) == 0) {
            g_Pex[t] = superExcl;
        } else {
            // + first 100 days of super-chunk c2: 12 x 8-day + 4 days from r
            float h = 0.0f;
            int b = c2 * 25;
#pragma unroll
            for (int i = 0; i < 12; ++i) h += s8[b + i];
            int d = (c2 * 200) + 96;
            h += (log1p_poly(r[d] - 1.0f) + log1p_poly(r[d + 1] - 1.0f))
               + (log1p_poly(r[d + 2] - 1.0f) + log1p_poly(r[d + 3] - 1.0f));
            g_Pex[t] = superExcl + h;
        }
    }
}

// ---- main kernel: QS=4 samples/thread, two f32x2 windows, STG.128 (.cs) ----
// Identical compute to R8/R10 (measured 38.7-39.6us). The PDL wait is placed
// as late as possible: all prep-independent work (pir, coefs, r window loads,
// backward-walk multipliers) happens BEFORE the wait; only the g_Pex read and
// the dependent window chain sit after it.
__global__ void __launch_bounds__(128) main_kernel(
    const float* __restrict__ r,      // (T,)
    const float* __restrict__ warm,   // (J,S)
    const float* __restrict__ Ts,     // (S,)
    const float* __restrict__ rho,    // (S,)
    const float* __restrict__ pi,     // (J,S)
    u64* __restrict__ out,            // (T, S/2) packed f32x2
    int T, int S)
{
    int q = blockIdx.x * blockDim.x + threadIdx.x;   // quad index
    int nquads = S >> 2;
    if (q >= nquads) {
        asm volatile("griddepcontrol.wait;" ::: "memory");
        return;
    }
    int c  = blockIdx.y;
    int d0 = c * DCH;

    float4 Ts4  = ((const float4*)Ts)[q];
    float4 rho4 = ((const float4*)rho)[q];
    float t0 = 1.0f / Ts4.x, t1 = 1.0f / Ts4.y;
    float t2 = 1.0f / Ts4.z, t3 = 1.0f / Ts4.w;

    u64 pirA[JW], pirB[JW];
#pragma unroll
    for (int j = 0; j < JW; ++j) {
        float4 p4 = ((const float4*)(pi + j * S))[q];
        pirA[j] = pk2(p4.x * rho4.x, p4.y * rho4.y);
        pirB[j] = pk2(p4.z * rho4.z, p4.w * rho4.w);
    }

    const u64 C1A = pk2(t0, t1), C1B = pk2(t2, t3);
    const u64 C2A = pk2(0.5f * t0 * (t0 - 1.0f), 0.5f * t1 * (t1 - 1.0f));
    const u64 C2B = pk2(0.5f * t2 * (t2 - 1.0f), 0.5f * t3 * (t3 - 1.0f));
    const u64 ONE2 = pk2(1.0f, 1.0f);

    u64 winA[JW], winB[JW];
    if (c == 0) {
#pragma unroll
        for (int j = 0; j < JW; ++j) {
            float4 w4 = ((const float4*)(warm + (JW - 1 - j) * S))[q];
            winA[j] = pk2(w4.x, w4.y);
            winB[j] = pk2(w4.z, w4.w);
        }
        asm volatile("griddepcontrol.wait;" ::: "memory");  // no prep data used
    } else {
        float4 wl4 = ((const float4*)(warm + (JW - 1) * S))[q];
        // --- prep-independent: window-day loads + backward multipliers ---
        // (1+v)^(-t) ~= 1 - t v + t(t+1)/2 v^2 - t(t+1)(t+2)/6 v^3
        u64 B1A = pk2(-t0, -t1), B1B = pk2(-t2, -t3);
        u64 B2A = pk2(0.5f * t0 * (t0 + 1.0f), 0.5f * t1 * (t1 + 1.0f));
        u64 B2B = pk2(0.5f * t2 * (t2 + 1.0f), 0.5f * t3 * (t3 + 1.0f));
        u64 B3A = pk2(-t0 * (t0 + 1.0f) * (t0 + 2.0f) / 6.0f,
                      -t1 * (t1 + 1.0f) * (t1 + 2.0f) / 6.0f);
        u64 B3B = pk2(-t2 * (t2 + 1.0f) * (t2 + 2.0f) / 6.0f,
                      -t3 * (t3 + 1.0f) * (t3 + 2.0f) / 6.0f);
        u64 eA[JW - 1], eB[JW - 1];
#pragma unroll
        for (int j = 1; j < JW; ++j) {
            float v = r[d0 - j] - 1.0f;
            u64 v2 = pk2(v, v);
            eA[j - 1] = fma2(v2, fma2(v2, fma2(v2, B3A, B2A), B1A), ONE2);
            eB[j - 1] = fma2(v2, fma2(v2, fma2(v2, B3B, B2B), B1B), ONE2);
        }
        // --- prep-dependent: anchor + window chain ---
        asm volatile("griddepcontrol.wait;" ::: "memory");
        float Pex = g_Pex[c];                 // sum log r[0..d0-1]
        winA[0] = pk2(wl4.x * __expf(Pex * t0), wl4.y * __expf(Pex * t1));
        winB[0] = pk2(wl4.z * __expf(Pex * t2), wl4.w * __expf(Pex * t3));
#pragma unroll
        for (int j = 1; j < JW; ++j) {
            winA[j] = mul2(winA[j - 1], eA[j - 1]);
            winB[j] = mul2(winB[j - 1], eB[j - 1]);
        }
    }
    u64 aA = winA[0], aB = winB[0];

    const float4* R4 = (const float4*)(r + d0);   // d0*4B is 400B-aligned
    u64* o = out + ((size_t)d0 * nquads + q) * 2;
    const size_t ostep = (size_t)nquads * 2;

#define STEP(rv) do {                                               \
        u64 mA0 = mul2(pirA[0], winA[0]);                           \
        u64 mA1 = mul2(pirA[1], winA[1]);                           \
        u64 mB0 = mul2(pirB[0], winB[0]);                           \
        u64 mB1 = mul2(pirB[1], winB[1]);                           \
        mA0 = fma2(pirA[2], winA[2], mA0);                          \
        mA1 = fma2(pirA[3], winA[3], mA1);                          \
        mB0 = fma2(pirB[2], winB[2], mB0);                          \
        mB1 = fma2(pirB[3], winB[3], mB1);                          \
        mA0 = fma2(pirA[4], winA[4], mA0);                          \
        mA1 = fma2(pirA[5], winA[5], mA1);                          \
        mB0 = fma2(pirB[4], winB[4], mB0);                          \
        mB1 = fma2(pirB[5], winB[5], mB1);                          \
        mA0 = fma2(pirA[6], winA[6], mA0);                          \
        mA1 = fma2(pirA[7], winA[7], mA1);                          \
        mB0 = fma2(pirB[6], winB[6], mB0);                          \
        mB1 = fma2(pirB[7], winB[7], mB1);                          \
        mA0 = fma2(pirA[8], winA[8], mA0);                          \
        mA1 = fma2(pirA[9], winA[9], mA1);                          \
        mB0 = fma2(pirB[8], winB[8], mB0);                          \
        mB1 = fma2(pirB[9], winB[9], mB1);                          \
        stcs128(o, add2(mA0, mA1), add2(mB0, mB1));                 \
        o += ostep;                                                 \
        float vv = (rv) - 1.0f;                                     \
        u64 v2 = pk2(vv, vv);                                       \
        u64 eAx = fma2(v2, fma2(v2, C2A, C1A), ONE2);               \
        u64 eBx = fma2(v2, fma2(v2, C2B, C1B), ONE2);               \
        aA = mul2(aA, eAx);                                         \
        aB = mul2(aB, eBx);                                         \
        _Pragma("unroll")                                           \
        for (int j = JW - 1; j > 0; --j) {                          \
            winA[j] = winA[j - 1];                                  \
            winB[j] = winB[j - 1];                                  \
        }                                                           \
        winA[0] = aA;                                               \
        winB[0] = aB;                                               \
    } while (0)

    if (d0 + DCH <= T) {
        // 25 iters of 4 days; unroll 5 -> 20 days/body = 2 full window rotations
#pragma unroll 5
        for (int it = 0; it < DCH / 4; ++it) {
            float4 L = R4[it];
            STEP(L.x);
            STEP(L.y);
            STEP(L.z);
            STEP(L.w);
        }
    } else {
        for (int d = d0; d < T; ++d) {
            float rv = r[d];
            STEP(rv);
        }
    }
#undef STEP
}

extern "C" void kernel_launch(void* const* d_in, const int* in_sizes, int n_in,
                              void* d_out, int out_size) {
    const float* r    = (const float*)d_in[0];  // (1,T)
    const float* warm = (const float*)d_in[1];  // (J,S)
    const float* Ts   = (const float*)d_in[2];  // (S,)
    const float* rho  = (const float*)d_in[3];  // (S,)
    const float* pi   = (const float*)d_in[4];  // (J,S)

    int T = in_sizes[0];
    int S = in_sizes[2];
    int nch = (T + DCH - 1) / DCH;

    prep_kernel<<<1, 1024>>>(r, T, nch);

    int nquads = S / 4;
    dim3 grid((nquads + 127) / 128, nch);

    // PDL launch of main: may begin scheduling while prep runs; the
    // griddepcontrol.wait inside orders the g_Pex read after prep completes.
    cudaLaunchConfig_t cfg = {};
    cfg.gridDim = grid;
    cfg.blockDim = dim3(128, 1, 1);
    cfg.dynamicSmemBytes = 0;
    cfg.stream = 0;
    cudaLaunchAttribute at[1];
    at[0].id = cudaLaunchAttributeProgrammaticStreamSerialization;
    at[0].val.programmaticStreamSerializationAllowed = 1;
    cfg.attrs = at;
    cfg.numAttrs = 1;

    cudaError_t e = cudaLaunchKernelEx(&cfg, main_kernel,
                                       r, warm, Ts, rho, pi, (u64*)d_out, T, S);
    if (e != cudaSuccess) {
        // fallback: plain serial launch (identical compute path)
        main_kernel<<<grid, 128>>>(r, warm, Ts, rho, pi, (u64*)d_out, T, S);
    }
}

// round 13
// speedup vs baseline: 1.1062x; 1.0052x over previous
#include <cuda_runtime.h>
#include <math.h>

#define JW 10
#define DCH 100          // days per chunk (T=50000 -> 500 chunks)
#define MAXCH 1024
#define PKMAX 13         // prep prefetch depth: covers T <= 13*4096 = 53248

// Scratch (allocation-free rule: __device__ globals)
__device__ float g_Pex[MAXCH];   // exclusive prefix of log r at chunk starts

typedef unsigned long long u64;

// ---- packed f32x2 helpers (sm_103a) ----
__device__ __forceinline__ u64 pk2(float lo, float hi) {
    u64 r; asm("mov.b64 %0, {%1, %2};" : "=l"(r) : "f"(lo), "f"(hi)); return r;
}
__device__ __forceinline__ u64 mul2(u64 a, u64 b) {
    u64 d; asm("mul.rn.f32x2 %0, %1, %2;" : "=l"(d) : "l"(a), "l"(b)); return d;
}
__device__ __forceinline__ u64 fma2(u64 a, u64 b, u64 c) {
    u64 d; asm("fma.rn.f32x2 %0, %1, %2, %3;" : "=l"(d) : "l"(a), "l"(b), "l"(c)); return d;
}
__device__ __forceinline__ u64 add2(u64 a, u64 b) {
    u64 d; asm("add.rn.f32x2 %0, %1, %2;" : "=l"(d) : "l"(a), "l"(b)); return d;
}
// 16-byte streaming store (evict-first): proven best in R8/R10/R12
__device__ __forceinline__ void stcs128(u64* p, u64 lo, u64 hi) {
    asm volatile("st.global.cs.v2.b64 [%0], {%1, %2};"
                 :: "l"(p), "l"(lo), "l"(hi) : "memory");
}

// log(1+x), |x| <= ~0.011: degree-5 poly, abs err ~1e-9
__device__ __forceinline__ float log1p_poly(float x) {
    float p = fmaf(x, 0.2f, -0.25f);
    p = fmaf(x, p, 1.0f / 3.0f);
    p = fmaf(x, p, -0.5f);
    p = fmaf(x, p, 1.0f);
    return x * p;
}

// ---- prep (single block, coalesced, MLP-prefetched) — R12-proven ----
__global__ void __launch_bounds__(1024) prep_kernel(const float* __restrict__ r,
                                                    int T, int nch) {
    // PDL: let the dependent (main) grid begin scheduling immediately.
    asm volatile("griddepcontrol.launch_dependents;" ::: "memory");

    __shared__ float s8[6272];    // 8-day log-sums: ceil(T/8) <= 6250
    __shared__ float cs[512];     // 200-day super-chunk sums
    int t = threadIdx.x;

    int n4 = (T + 3) >> 2;        // # float4 groups (T=50000 -> 12500)
    int n8 = (T + 7) >> 3;        // # 8-day groups  (6250)

    // Prefetch ALL rounds up-front (MLP ~= PKMAX) -- one DRAM latency wall.
    float4 buf[PKMAX];
#pragma unroll
    for (int k = 0; k < PKMAX; ++k) {
        int i4 = k * 1024 + t;
        buf[k] = make_float4(1.0f, 1.0f, 1.0f, 1.0f);
        if (i4 * 4 + 4 <= T) buf[k] = *(const float4*)(r + i4 * 4);
    }
#pragma unroll
    for (int k = 0; k < PKMAX; ++k) {
        int i4 = k * 1024 + t;
        float v = 0.0f;
        if (i4 < n4) {
            int d = i4 * 4;
            if (d + 4 <= T) {
                float4 rv = buf[k];
                v = (log1p_poly(rv.x - 1.0f) + log1p_poly(rv.y - 1.0f))
                  + (log1p_poly(rv.z - 1.0f) + log1p_poly(rv.w - 1.0f));
            } else {
                for (int i = d; i < T; ++i) v += log1p_poly(r[i] - 1.0f);
            }
        }
        float w = v + __shfl_xor_sync(0xffffffffu, v, 1);
        int i8 = i4 >> 1;
        if ((t & 1) == 0 && i4 < n4 && i8 < n8) s8[i8] = w;
    }
    // fallback for T beyond prefetch reach (not taken at T=50000)
    for (int k = PKMAX; k < (n4 + 1023) / 1024; ++k) {
        int i4 = k * 1024 + t;
        float v = 0.0f;
        if (i4 < n4) {
            int d = i4 * 4;
            if (d + 4 <= T) {
                float4 rv = *(const float4*)(r + d);
                v = (log1p_poly(rv.x - 1.0f) + log1p_poly(rv.y - 1.0f))
                  + (log1p_poly(rv.z - 1.0f) + log1p_poly(rv.w - 1.0f));
            } else {
                for (int i = d; i < T; ++i) v += log1p_poly(r[i] - 1.0f);
            }
        }
        float w = v + __shfl_xor_sync(0xffffffffu, v, 1);
        int i8 = i4 >> 1;
        if ((t & 1) == 0 && i4 < n4 && i8 < n8) s8[i8] = w;
    }
    __syncthreads();

    // 200-day super-chunk sums (25 x 8-day groups each)
    if (t < 512) {
        float s = 0.0f;
        int c2 = t;
        if (c2 < (nch + 1) / 2) {
            int base = c2 * 25;
            float a0 = 0.f, a1 = 0.f, a2 = 0.f, a3 = 0.f, a4 = 0.f;
#pragma unroll
            for (int i = 0; i < 25; i += 5) {
                a0 += s8[base + i];
                a1 += s8[base + i + 1];
                a2 += s8[base + i + 2];
                a3 += s8[base + i + 3];
                a4 += s8[base + i + 4];
            }
            s = ((a0 + a1) + (a2 + a3)) + a4;
        }
        cs[t] = s;
    }
    __syncthreads();

    // Hillis-Steele inclusive scan over 512 super-chunk sums
#pragma unroll
    for (int off = 1; off < 512; off <<= 1) {
        float u = 0.0f;
        if (t < 512 && t >= off) u = cs[t - off];
        __syncthreads();
        if (t < 512) cs[t] += u;
        __syncthreads();
    }
    // emit 100-day-chunk exclusive prefixes
    if (t < nch) {
        int c2 = t >> 1;
        float superExcl = (c2 == 0) ? 0.0f : cs[c2 - 1];
        if ((t & 1) == 0) {
            g_Pex[t] = superExcl;
        } else {
            // + first 100 days of super-chunk c2: 12 x 8-day + 4 days from r
            float h = 0.0f;
            int b = c2 * 25;
#pragma unroll
            for (int i = 0; i < 12; ++i) h += s8[b + i];
            int d = (c2 * 200) + 96;
            h += (log1p_poly(r[d] - 1.0f) + log1p_poly(r[d + 1] - 1.0f))
               + (log1p_poly(r[d + 2] - 1.0f) + log1p_poly(r[d + 3] - 1.0f));
            g_Pex[t] = superExcl + h;
        }
    }
}

// ---- main kernel: QS=4, two f32x2 windows, STG.128 (.cs), 4 blocks/SM ----
// __launch_bounds__(128, 4): cap regs at 128 so 4 CTAs fit per SM (16 warps,
// +33% warps/SMSP) to cover the 5-deep FFMA2 dependency chains.
__global__ void __launch_bounds__(128, 4) main_kernel(
    const float* __restrict__ r,      // (T,)
    const float* __restrict__ warm,   // (J,S)
    const float* __restrict__ Ts,     // (S,)
    const float* __restrict__ rho,    // (S,)
    const float* __restrict__ pi,     // (J,S)
    u64* __restrict__ out,            // (T, S/2) packed f32x2
    int T, int S)
{
    int q = blockIdx.x * blockDim.x + threadIdx.x;   // quad index
    int nquads = S >> 2;
    if (q >= nquads) {
        asm volatile("griddepcontrol.wait;" ::: "memory");
        return;
    }
    int c  = blockIdx.y;
    int d0 = c * DCH;

    float4 Ts4  = ((const float4*)Ts)[q];
    float4 rho4 = ((const float4*)rho)[q];
    float t0 = 1.0f / Ts4.x, t1 = 1.0f / Ts4.y;
    float t2 = 1.0f / Ts4.z, t3 = 1.0f / Ts4.w;

    u64 pirA[JW], pirB[JW];
#pragma unroll
    for (int j = 0; j < JW; ++j) {
        float4 p4 = ((const float4*)(pi + j * S))[q];
        pirA[j] = pk2(p4.x * rho4.x, p4.y * rho4.y);
        pirB[j] = pk2(p4.z * rho4.z, p4.w * rho4.w);
    }

    const u64 C1A = pk2(t0, t1), C1B = pk2(t2, t3);
    const u64 C2A = pk2(0.5f * t0 * (t0 - 1.0f), 0.5f * t1 * (t1 - 1.0f));
    const u64 C2B = pk2(0.5f * t2 * (t2 - 1.0f), 0.5f * t3 * (t3 - 1.0f));
    const u64 ONE2 = pk2(1.0f, 1.0f);

    u64 winA[JW], winB[JW];
    if (c == 0) {
#pragma unroll
        for (int j = 0; j < JW; ++j) {
            float4 w4 = ((const float4*)(warm + (JW - 1 - j) * S))[q];
            winA[j] = pk2(w4.x, w4.y);
            winB[j] = pk2(w4.z, w4.w);
        }
        asm volatile("griddepcontrol.wait;" ::: "memory");  // no prep data used
    } else {
        float4 wl4 = ((const float4*)(warm + (JW - 1) * S))[q];
        // --- prep-independent: window-day loads + backward multipliers ---
        // (1+v)^(-t) ~= 1 - t v + t(t+1)/2 v^2 - t(t+1)(t+2)/6 v^3
        u64 B1A = pk2(-t0, -t1), B1B = pk2(-t2, -t3);
        u64 B2A = pk2(0.5f * t0 * (t0 + 1.0f), 0.5f * t1 * (t1 + 1.0f));
        u64 B2B = pk2(0.5f * t2 * (t2 + 1.0f), 0.5f * t3 * (t3 + 1.0f));
        u64 B3A = pk2(-t0 * (t0 + 1.0f) * (t0 + 2.0f) / 6.0f,
                      -t1 * (t1 + 1.0f) * (t1 + 2.0f) / 6.0f);
        u64 B3B = pk2(-t2 * (t2 + 1.0f) * (t2 + 2.0f) / 6.0f,
                      -t3 * (t3 + 1.0f) * (t3 + 2.0f) / 6.0f);
        u64 eA[JW - 1], eB[JW - 1];
#pragma unroll
        for (int j = 1; j < JW; ++j) {
            float v = r[d0 - j] - 1.0f;
            u64 v2 = pk2(v, v);
            eA[j - 1] = fma2(v2, fma2(v2, fma2(v2, B3A, B2A), B1A), ONE2);
            eB[j - 1] = fma2(v2, fma2(v2, fma2(v2, B3B, B2B), B1B), ONE2);
        }
        // --- prep-dependent: anchor + window chain ---
        asm volatile("griddepcontrol.wait;" ::: "memory");
        float Pex = g_Pex[c];                 // sum log r[0..d0-1]
        winA[0] = pk2(wl4.x * __expf(Pex * t0), wl4.y * __expf(Pex * t1));
        winB[0] = pk2(wl4.z * __expf(Pex * t2), wl4.w * __expf(Pex * t3));
#pragma unroll
        for (int j = 1; j < JW; ++j) {
            winA[j] = mul2(winA[j - 1], eA[j - 1]);
            winB[j] = mul2(winB[j - 1], eB[j - 1]);
        }
    }
    u64 aA = winA[0], aB = winB[0];

    const float4* R4 = (const float4*)(r + d0);   // d0*4B is 400B-aligned
    u64* o = out + ((size_t)d0 * nquads + q) * 2;
    const size_t ostep = (size_t)nquads * 2;

#define STEP(rv) do {                                               \
        u64 mA0 = mul2(pirA[0], winA[0]);                           \
        u64 mA1 = mul2(pirA[1], winA[1]);                           \
        u64 mB0 = mul2(pirB[0], winB[0]);                           \
        u64 mB1 = mul2(pirB[1], winB[1]);                           \
        mA0 = fma2(pirA[2], winA[2], mA0);                          \
        mA1 = fma2(pirA[3], winA[3], mA1);                          \
        mB0 = fma2(pirB[2], winB[2], mB0);                          \
        mB1 = fma2(pirB[3], winB[3], mB1);                          \
        mA0 = fma2(pirA[4], winA[4], mA0);                          \
        mA1 = fma2(pirA[5], winA[5], mA1);                          \
        mB0 = fma2(pirB[4], winB[4], mB0);                          \
        mB1 = fma2(pirB[5], winB[5], mB1);                          \
        mA0 = fma2(pirA[6], winA[6], mA0);                          \
        mA1 = fma2(pirA[7], winA[7], mA1);                          \
        mB0 = fma2(pirB[6], winB[6], mB0);                          \
        mB1 = fma2(pirB[7], winB[7], mB1);                          \
        mA0 = fma2(pirA[8], winA[8], mA0);                          \
        mA1 = fma2(pirA[9], winA[9], mA1);                          \
        mB0 = fma2(pirB[8], winB[8], mB0);                          \
        mB1 = fma2(pirB[9], winB[9], mB1);                          \
        stcs128(o, add2(mA0, mA1), add2(mB0, mB1));                 \
        o += ostep;                                                 \
        float vv = (rv) - 1.0f;                                     \
        u64 v2 = pk2(vv, vv);                                       \
        u64 eAx = fma2(v2, fma2(v2, C2A, C1A), ONE2);               \
        u64 eBx = fma2(v2, fma2(v2, C2B, C1B), ONE2);               \
        aA = mul2(aA, eAx);                                         \
        aB = mul2(aB, eBx);                                         \
        _Pragma("unroll")                                           \
        for (int j = JW - 1; j > 0; --j) {                          \
            winA[j] = winA[j - 1];                                  \
            winB[j] = winB[j - 1];                                  \
        }                                                           \
        winA[0] = aA;                                               \
        winB[0] = aB;                                               \
    } while (0)

    if (d0 + DCH <= T) {
        // 25 iters of 4 days; unroll 5 -> 20 days/body = 2 full window rotations
#pragma unroll 5
        for (int it = 0; it < DCH / 4; ++it) {
            float4 L = R4[it];
            STEP(L.x);
            STEP(L.y);
            STEP(L.z);
            STEP(L.w);
        }
    } else {
        for (int d = d0; d < T; ++d) {
            float rv = r[d];
            STEP(rv);
        }
    }
#undef STEP
}

extern "C" void kernel_launch(void* const* d_in, const int* in_sizes, int n_in,
                              void* d_out, int out_size) {
    const float* r    = (const float*)d_in[0];  // (1,T)
    const float* warm = (const float*)d_in[1];  // (J,S)
    const float* Ts   = (const float*)d_in[2];  // (S,)
    const float* rho  = (const float*)d_in[3];  // (S,)
    const float* pi   = (const float*)d_in[4];  // (J,S)

    int T = in_sizes[0];
    int S = in_sizes[2];
    int nch = (T + DCH - 1) / DCH;

    prep_kernel<<<1, 1024>>>(r, T, nch);

    int nquads = S / 4;
    dim3 grid((nquads + 127) / 128, nch);

    // PDL launch of main: may begin scheduling while prep runs; the
    // griddepcontrol.wait inside orders the g_Pex read after prep completes.
    cudaLaunchConfig_t cfg = {};
    cfg.gridDim = grid;
    cfg.blockDim = dim3(128, 1, 1);
    cfg.dynamicSmemBytes = 0;
    cfg.stream = 0;
    cudaLaunchAttribute at[1];
    at[0].id = cudaLaunchAttributeProgrammaticStreamSerialization;
    at[0].val.programmaticStreamSerializationAllowed = 1;
    cfg.attrs = at;
    cfg.numAttrs = 1;

    cudaError_t e = cudaLaunchKernelEx(&cfg, main_kernel,
                                       r, warm, Ts, rho, pi, (u64*)d_out, T, S);
    if (e != cudaSuccess) {
        // fallback: plain serial launch (identical compute path)
        main_kernel<<<grid, 128>>>(r, warm, Ts, rho, pi, (u64*)d_out, T, S);
    }
}

// round 14
// speedup vs baseline: 1.1506x; 1.0402x over previous
#include <cuda_runtime.h>
#include <math.h>

#define JW 10
#define DCH 100          // days per chunk (T=50000 -> 500 chunks)
#define MAXCH 1024
#define PKMAX 13         // prep prefetch depth: covers T <= 13*4096 = 53248

// Scratch (allocation-free rule: __device__ globals)
__device__ float g_Pex[MAXCH];   // exclusive prefix of log r at chunk starts

typedef unsigned long long u64;

// ---- packed f32x2 helpers (sm_103a) ----
__device__ __forceinline__ u64 pk2(float lo, float hi) {
    u64 r; asm("mov.b64 %0, {%1, %2};" : "=l"(r) : "f"(lo), "f"(hi)); return r;
}
__device__ __forceinline__ u64 mul2(u64 a, u64 b) {
    u64 d; asm("mul.rn.f32x2 %0, %1, %2;" : "=l"(d) : "l"(a), "l"(b)); return d;
}
__device__ __forceinline__ u64 fma2(u64 a, u64 b, u64 c) {
    u64 d; asm("fma.rn.f32x2 %0, %1, %2, %3;" : "=l"(d) : "l"(a), "l"(b), "l"(c)); return d;
}
__device__ __forceinline__ u64 add2(u64 a, u64 b) {
    u64 d; asm("add.rn.f32x2 %0, %1, %2;" : "=l"(d) : "l"(a), "l"(b)); return d;
}
// 16-byte streaming store (evict-first): proven best in R8/R10/R12/R13
__device__ __forceinline__ void stcs128(u64* p, u64 lo, u64 hi) {
    asm volatile("st.global.cs.v2.b64 [%0], {%1, %2};"
                 :: "l"(p), "l"(lo), "l"(hi) : "memory");
}

// log(1+x), |x| <= ~0.011: degree-5 poly, abs err ~1e-9
__device__ __forceinline__ float log1p_poly(float x) {
    float p = fmaf(x, 0.2f, -0.25f);
    p = fmaf(x, p, 1.0f / 3.0f);
    p = fmaf(x, p, -0.5f);
    p = fmaf(x, p, 1.0f);
    return x * p;
}

// ---- prep (single block, coalesced, MLP-prefetched) — R12/R13-proven ----
__global__ void __launch_bounds__(1024) prep_kernel(const float* __restrict__ r,
                                                    int T, int nch) {
    // PDL: let the dependent (main) grid begin scheduling immediately.
    asm volatile("griddepcontrol.launch_dependents;" ::: "memory");

    __shared__ float s8[6272];    // 8-day log-sums: ceil(T/8) <= 6250
    __shared__ float cs[512];     // 200-day super-chunk sums
    int t = threadIdx.x;

    int n4 = (T + 3) >> 2;        // # float4 groups (T=50000 -> 12500)
    int n8 = (T + 7) >> 3;        // # 8-day groups  (6250)

    // Prefetch ALL rounds up-front (MLP ~= PKMAX) -- one DRAM latency wall.
    float4 buf[PKMAX];
#pragma unroll
    for (int k = 0; k < PKMAX; ++k) {
        int i4 = k * 1024 + t;
        buf[k] = make_float4(1.0f, 1.0f, 1.0f, 1.0f);
        if (i4 * 4 + 4 <= T) buf[k] = *(const float4*)(r + i4 * 4);
    }
#pragma unroll
    for (int k = 0; k < PKMAX; ++k) {
        int i4 = k * 1024 + t;
        float v = 0.0f;
        if (i4 < n4) {
            int d = i4 * 4;
            if (d + 4 <= T) {
                float4 rv = buf[k];
                v = (log1p_poly(rv.x - 1.0f) + log1p_poly(rv.y - 1.0f))
                  + (log1p_poly(rv.z - 1.0f) + log1p_poly(rv.w - 1.0f));
            } else {
                for (int i = d; i < T; ++i) v += log1p_poly(r[i] - 1.0f);
            }
        }
        float w = v + __shfl_xor_sync(0xffffffffu, v, 1);
        int i8 = i4 >> 1;
        if ((t & 1) == 0 && i4 < n4 && i8 < n8) s8[i8] = w;
    }
    // fallback for T beyond prefetch reach (not taken at T=50000)
    for (int k = PKMAX; k < (n4 + 1023) / 1024; ++k) {
        int i4 = k * 1024 + t;
        float v = 0.0f;
        if (i4 < n4) {
            int d = i4 * 4;
            if (d + 4 <= T) {
                float4 rv = *(const float4*)(r + d);
                v = (log1p_poly(rv.x - 1.0f) + log1p_poly(rv.y - 1.0f))
                  + (log1p_poly(rv.z - 1.0f) + log1p_poly(rv.w - 1.0f));
            } else {
                for (int i = d; i < T; ++i) v += log1p_poly(r[i] - 1.0f);
            }
        }
        float w = v + __shfl_xor_sync(0xffffffffu, v, 1);
        int i8 = i4 >> 1;
        if ((t & 1) == 0 && i4 < n4 && i8 < n8) s8[i8] = w;
    }
    __syncthreads();

    // 200-day super-chunk sums (25 x 8-day groups each)
    if (t < 512) {
        float s = 0.0f;
        int c2 = t;
        if (c2 < (nch + 1) / 2) {
            int base = c2 * 25;
            float a0 = 0.f, a1 = 0.f, a2 = 0.f, a3 = 0.f, a4 = 0.f;
#pragma unroll
            for (int i = 0; i < 25; i += 5) {
                a0 += s8[base + i];
                a1 += s8[base + i + 1];
                a2 += s8[base + i + 2];
                a3 += s8[base + i + 3];
                a4 += s8[base + i + 4];
            }
            s = ((a0 + a1) + (a2 + a3)) + a4;
        }
        cs[t] = s;
    }
    __syncthreads();

    // Hillis-Steele inclusive scan over 512 super-chunk sums
#pragma unroll
    for (int off = 1; off < 512; off <<= 1) {
        float u = 0.0f;
        if (t < 512 && t >= off) u = cs[t - off];
        __syncthreads();
        if (t < 512) cs[t] += u;
        __syncthreads();
    }
    // emit 100-day-chunk exclusive prefixes
    if (t < nch) {
        int c2 = t >> 1;
        float superExcl = (c2 == 0) ? 0.0f : cs[c2 - 1];
        if ((t & 1) == 0) {
            g_Pex[t] = superExcl;
        } else {
            // + first 100 days of super-chunk c2: 12 x 8-day + 4 days from r
            float h = 0.0f;
            int b = c2 * 25;
#pragma unroll
            for (int i = 0; i < 12; ++i) h += s8[b + i];
            int d = (c2 * 200) + 96;
            h += (log1p_poly(r[d] - 1.0f) + log1p_poly(r[d + 1] - 1.0f))
               + (log1p_poly(r[d + 2] - 1.0f) + log1p_poly(r[d + 3] - 1.0f));
            g_Pex[t] = superExcl + h;
        }
    }
}

// ---- main kernel: QS=4, two f32x2 windows, STG.128 (.cs), 4 blocks/SM ----
// Template NQ: compile-time nquads (0 = runtime). With NQ=250 the output
// stride is constexpr -> immediate-offset STG addressing, no per-day IADD64.
template <int NQ>
__global__ void __launch_bounds__(128, 4) main_kernel(
    const float* __restrict__ r,      // (T,)
    const float* __restrict__ warm,   // (J,S)
    const float* __restrict__ Ts,     // (S,)
    const float* __restrict__ rho,    // (S,)
    const float* __restrict__ pi,     // (J,S)
    u64* __restrict__ out,            // (T, S/2) packed f32x2
    int T, int S)
{
    const int nquads = (NQ > 0) ? NQ : (S >> 2);
    int q = blockIdx.x * blockDim.x + threadIdx.x;   // quad index
    if (q >= nquads) {
        asm volatile("griddepcontrol.wait;" ::: "memory");
        return;
    }
    int c  = blockIdx.y;
    int d0 = c * DCH;

    float4 Ts4  = ((const float4*)Ts)[q];
    float4 rho4 = ((const float4*)rho)[q];
    float t0 = 1.0f / Ts4.x, t1 = 1.0f / Ts4.y;
    float t2 = 1.0f / Ts4.z, t3 = 1.0f / Ts4.w;

    u64 pirA[JW], pirB[JW];
#pragma unroll
    for (int j = 0; j < JW; ++j) {
        float4 p4 = ((const float4*)(pi + j * S))[q];
        pirA[j] = pk2(p4.x * rho4.x, p4.y * rho4.y);
        pirB[j] = pk2(p4.z * rho4.z, p4.w * rho4.w);
    }

    const u64 C1A = pk2(t0, t1), C1B = pk2(t2, t3);
    const u64 C2A = pk2(0.5f * t0 * (t0 - 1.0f), 0.5f * t1 * (t1 - 1.0f));
    const u64 C2B = pk2(0.5f * t2 * (t2 - 1.0f), 0.5f * t3 * (t3 - 1.0f));
    const u64 ONE2 = pk2(1.0f, 1.0f);

    u64 winA[JW], winB[JW];
    if (c == 0) {
#pragma unroll
        for (int j = 0; j < JW; ++j) {
            float4 w4 = ((const float4*)(warm + (JW - 1 - j) * S))[q];
            winA[j] = pk2(w4.x, w4.y);
            winB[j] = pk2(w4.z, w4.w);
        }
        asm volatile("griddepcontrol.wait;" ::: "memory");  // no prep data used
    } else {
        float4 wl4 = ((const float4*)(warm + (JW - 1) * S))[q];
        // --- prep-independent: window-day loads + backward multipliers ---
        // (1+v)^(-t) ~= 1 - t v + t(t+1)/2 v^2 - t(t+1)(t+2)/6 v^3
        u64 B1A = pk2(-t0, -t1), B1B = pk2(-t2, -t3);
        u64 B2A = pk2(0.5f * t0 * (t0 + 1.0f), 0.5f * t1 * (t1 + 1.0f));
        u64 B2B = pk2(0.5f * t2 * (t2 + 1.0f), 0.5f * t3 * (t3 + 1.0f));
        u64 B3A = pk2(-t0 * (t0 + 1.0f) * (t0 + 2.0f) / 6.0f,
                      -t1 * (t1 + 1.0f) * (t1 + 2.0f) / 6.0f);
        u64 B3B = pk2(-t2 * (t2 + 1.0f) * (t2 + 2.0f) / 6.0f,
                      -t3 * (t3 + 1.0f) * (t3 + 2.0f) / 6.0f);
        u64 eA[JW - 1], eB[JW - 1];
#pragma unroll
        for (int j = 1; j < JW; ++j) {
            float v = r[d0 - j] - 1.0f;
            u64 v2 = pk2(v, v);
            eA[j - 1] = fma2(v2, fma2(v2, fma2(v2, B3A, B2A), B1A), ONE2);
            eB[j - 1] = fma2(v2, fma2(v2, fma2(v2, B3B, B2B), B1B), ONE2);
        }
        // --- prep-dependent: anchor + window chain ---
        asm volatile("griddepcontrol.wait;" ::: "memory");
        float Pex = g_Pex[c];                 // sum log r[0..d0-1]
        winA[0] = pk2(wl4.x * __expf(Pex * t0), wl4.y * __expf(Pex * t1));
        winB[0] = pk2(wl4.z * __expf(Pex * t2), wl4.w * __expf(Pex * t3));
#pragma unroll
        for (int j = 1; j < JW; ++j) {
            winA[j] = mul2(winA[j - 1], eA[j - 1]);
            winB[j] = mul2(winB[j - 1], eB[j - 1]);
        }
    }
    u64 aA = winA[0], aB = winB[0];

    const float4* R4 = (const float4*)(r + d0);   // d0*4B is 400B-aligned
    u64* o = out + ((size_t)d0 * nquads + q) * 2;
    const size_t OST = (size_t)nquads * 2;        // constexpr when NQ>0

#define STEP(rv, k) do {                                            \
        u64 mA0 = mul2(pirA[0], winA[0]);                           \
        u64 mA1 = mul2(pirA[1], winA[1]);                           \
        u64 mB0 = mul2(pirB[0], winB[0]);                           \
        u64 mB1 = mul2(pirB[1], winB[1]);                           \
        mA0 = fma2(pirA[2], winA[2], mA0);                          \
        mA1 = fma2(pirA[3], winA[3], mA1);                          \
        mB0 = fma2(pirB[2], winB[2], mB0);                          \
        mB1 = fma2(pirB[3], winB[3], mB1);                          \
        mA0 = fma2(pirA[4], winA[4], mA0);                          \
        mA1 = fma2(pirA[5], winA[5], mA1);                          \
        mB0 = fma2(pirB[4], winB[4], mB0);                          \
        mB1 = fma2(pirB[5], winB[5], mB1);                          \
        mA0 = fma2(pirA[6], winA[6], mA0);                          \
        mA1 = fma2(pirA[7], winA[7], mA1);                          \
        mB0 = fma2(pirB[6], winB[6], mB0);                          \
        mB1 = fma2(pirB[7], winB[7], mB1);                          \
        mA0 = fma2(pirA[8], winA[8], mA0);                          \
        mA1 = fma2(pirA[9], winA[9], mA1);                          \
        mB0 = fma2(pirB[8], winB[8], mB0);                          \
        mB1 = fma2(pirB[9], winB[9], mB1);                          \
        stcs128(o + (size_t)(k) * OST, add2(mA0, mA1), add2(mB0, mB1)); \
        float vv = (rv) - 1.0f;                                     \
        u64 v2 = pk2(vv, vv);                                       \
        u64 eAx = fma2(v2, fma2(v2, C2A, C1A), ONE2);               \
        u64 eBx = fma2(v2, fma2(v2, C2B, C1B), ONE2);               \
        aA = mul2(aA, eAx);                                         \
        aB = mul2(aB, eBx);                                         \
        _Pragma("unroll")                                           \
        for (int j = JW - 1; j > 0; --j) {                          \
            winA[j] = winA[j - 1];                                  \
            winB[j] = winB[j - 1];                                  \
        }                                                           \
        winA[0] = aA;                                               \
        winB[0] = aB;                                               \
    } while (0)

    if (d0 + DCH <= T) {
        // 25 iters of 4 days; unroll 5 -> 20 days/body = 2 full window rotations
#pragma unroll 5
        for (int it = 0; it < DCH / 4; ++it) {
            float4 L = R4[it];
            STEP(L.x, 0);
            STEP(L.y, 1);
            STEP(L.z, 2);
            STEP(L.w, 3);
            o += 4 * OST;    // one pointer bump per 4 days (imm offsets above)
        }
    } else {
        for (int d = d0; d < T; ++d) {
            float rv = r[d];
            STEP(rv, 0);
            o += OST;
        }
    }
#undef STEP
}

extern "C" void kernel_launch(void* const* d_in, const int* in_sizes, int n_in,
                              void* d_out, int out_size) {
    const float* r    = (const float*)d_in[0];  // (1,T)
    const float* warm = (const float*)d_in[1];  // (J,S)
    const float* Ts   = (const float*)d_in[2];  // (S,)
    const float* rho  = (const float*)d_in[3];  // (S,)
    const float* pi   = (const float*)d_in[4];  // (J,S)

    int T = in_sizes[0];
    int S = in_sizes[2];
    int nch = (T + DCH - 1) / DCH;

    prep_kernel<<<1, 1024>>>(r, T, nch);

    int nquads = S / 4;
    dim3 grid((nquads + 127) / 128, nch);

    // PDL launch of main: may begin scheduling while prep runs; the
    // griddepcontrol.wait inside orders the g_Pex read after prep completes.
    cudaLaunchConfig_t cfg = {};
    cfg.gridDim = grid;
    cfg.blockDim = dim3(128, 1, 1);
    cfg.dynamicSmemBytes = 0;
    cfg.stream = 0;
    cudaLaunchAttribute at[1];
    at[0].id = cudaLaunchAttributeProgrammaticStreamSerialization;
    at[0].val.programmaticStreamSerializationAllowed = 1;
    cfg.attrs = at;
    cfg.numAttrs = 1;

    cudaError_t e;
    if (nquads == 250) {
        e = cudaLaunchKernelEx(&cfg, main_kernel<250>,
                               r, warm, Ts, rho, pi, (u64*)d_out, T, S);
        if (e != cudaSuccess)
            main_kernel<250><<<grid, 128>>>(r, warm, Ts, rho, pi,
                                            (u64*)d_out, T, S);
    } else {
        e = cudaLaunchKernelEx(&cfg, main_kernel<0>,
                               r, warm, Ts, rho, pi, (u64*)d_out, T, S);
        if (e != cudaSuccess)
            main_kernel<0><<<grid, 128>>>(r, warm, Ts, rho, pi,
                                          (u64*)d_out, T, S);
    }
}

// round 15
// speedup vs baseline: 1.1568x; 1.0054x over previous
#include <cuda_runtime.h>
#include <math.h>

#define JW 10
#define DCH 100          // days per chunk (T=50000 -> 500 chunks)
#define MAXCH 1024
#define PKMAX 13         // prep prefetch depth: covers T <= 13*4096 = 53248

// Scratch (allocation-free rule: __device__ globals)
__device__ float g_Pex[MAXCH];   // exclusive prefix of log r at chunk starts

typedef unsigned long long u64;

// ---- packed f32x2 helpers (sm_103a) ----
__device__ __forceinline__ u64 pk2(float lo, float hi) {
    u64 r; asm("mov.b64 %0, {%1, %2};" : "=l"(r) : "f"(lo), "f"(hi)); return r;
}
__device__ __forceinline__ u64 mul2(u64 a, u64 b) {
    u64 d; asm("mul.rn.f32x2 %0, %1, %2;" : "=l"(d) : "l"(a), "l"(b)); return d;
}
__device__ __forceinline__ u64 fma2(u64 a, u64 b, u64 c) {
    u64 d; asm("fma.rn.f32x2 %0, %1, %2, %3;" : "=l"(d) : "l"(a), "l"(b), "l"(c)); return d;
}
__device__ __forceinline__ u64 add2(u64 a, u64 b) {
    u64 d; asm("add.rn.f32x2 %0, %1, %2;" : "=l"(d) : "l"(a), "l"(b)); return d;
}
// 16-byte streaming store (evict-first): proven best in R8/R10/R12/R13/R14
__device__ __forceinline__ void stcs128(u64* p, u64 lo, u64 hi) {
    asm volatile("st.global.cs.v2.b64 [%0], {%1, %2};"
                 :: "l"(p), "l"(lo), "l"(hi) : "memory");
}

// log(1+x), |x| <= ~0.011: degree-4, trunc err x^5/5 ~ 2e-12/day,
// biased accumulation over 50K days <= 1e-7 abs — 30x under anchor budget.
__device__ __forceinline__ float log1p_poly(float x) {
    float p = fmaf(x, -0.25f, 1.0f / 3.0f);
    p = fmaf(x, p, -0.5f);
    p = fmaf(x, p, 1.0f);
    return x * p;
}

// ---- prep (single block, coalesced, MLP-prefetched, shuffle scan) ----
__global__ void __launch_bounds__(1024) prep_kernel(const float* __restrict__ r,
                                                    int T, int nch) {
    // PDL: let the dependent (main) grid begin scheduling immediately.
    asm volatile("griddepcontrol.launch_dependents;" ::: "memory");

    __shared__ float s8[6272];    // 8-day log-sums: ceil(T/8) <= 6250
    __shared__ float cs[256];     // 200-day super-chunk inclusive scan
    __shared__ float ws[8];       // per-warp scan sums
    int t = threadIdx.x;
    int lane = t & 31;
    int wid = t >> 5;

    int n4 = (T + 3) >> 2;        // # float4 groups (T=50000 -> 12500)
    int n8 = (T + 7) >> 3;        // # 8-day groups  (6250)

    // Prefetch ALL rounds up-front (MLP ~= PKMAX) -- one DRAM latency wall.
    float4 buf[PKMAX];
#pragma unroll
    for (int k = 0; k < PKMAX; ++k) {
        int i4 = k * 1024 + t;
        buf[k] = make_float4(1.0f, 1.0f, 1.0f, 1.0f);
        if (i4 * 4 + 4 <= T) buf[k] = *(const float4*)(r + i4 * 4);
    }
#pragma unroll
    for (int k = 0; k < PKMAX; ++k) {
        int i4 = k * 1024 + t;
        float v = 0.0f;
        if (i4 < n4) {
            int d = i4 * 4;
            if (d + 4 <= T) {
                float4 rv = buf[k];
                v = (log1p_poly(rv.x - 1.0f) + log1p_poly(rv.y - 1.0f))
                  + (log1p_poly(rv.z - 1.0f) + log1p_poly(rv.w - 1.0f));
            } else {
                for (int i = d; i < T; ++i) v += log1p_poly(r[i] - 1.0f);
            }
        }
        float w = v + __shfl_xor_sync(0xffffffffu, v, 1);
        int i8 = i4 >> 1;
        if ((t & 1) == 0 && i4 < n4 && i8 < n8) s8[i8] = w;
    }
    // fallback for T beyond prefetch reach (not taken at T=50000)
    for (int k = PKMAX; k < (n4 + 1023) / 1024; ++k) {
        int i4 = k * 1024 + t;
        float v = 0.0f;
        if (i4 < n4) {
            int d = i4 * 4;
            if (d + 4 <= T) {
                float4 rv = *(const float4*)(r + d);
                v = (log1p_poly(rv.x - 1.0f) + log1p_poly(rv.y - 1.0f))
                  + (log1p_poly(rv.z - 1.0f) + log1p_poly(rv.w - 1.0f));
            } else {
                for (int i = d; i < T; ++i) v += log1p_poly(r[i] - 1.0f);
            }
        }
        float w = v + __shfl_xor_sync(0xffffffffu, v, 1);
        int i8 = i4 >> 1;
        if ((t & 1) == 0 && i4 < n4 && i8 < n8) s8[i8] = w;
    }
    __syncthreads();

    // 200-day super-chunk sums + shuffle-based inclusive scan (<=256 supers)
    int nsuper = (nch + 1) / 2;    // 250 for T=50000
    if (t < 256) {
        float s = 0.0f;
        if (t < nsuper) {
            int base = t * 25;     // 25 x 8-day groups per 200 days
            float a0 = 0.f, a1 = 0.f, a2 = 0.f, a3 = 0.f, a4 = 0.f;
#pragma unroll
            for (int i = 0; i < 25; i += 5) {
                a0 += s8[base + i];
                a1 += s8[base + i + 1];
                a2 += s8[base + i + 2];
                a3 += s8[base + i + 3];
                a4 += s8[base + i + 4];
            }
            s = ((a0 + a1) + (a2 + a3)) + a4;
        }
        // warp-inclusive scan
        float v = s;
#pragma unroll
        for (int off = 1; off < 32; off <<= 1) {
            float u = __shfl_up_sync(0xffffffffu, v, off);
            if (lane >= off) v += u;
        }
        if (lane == 31) ws[wid] = v;
        cs[t] = v;                 // provisional (within-warp inclusive)
    }
    __syncthreads();
    if (t < 32) {
        // scan the 8 warp sums in one warp
        float w = (lane < 8) ? ws[lane] : 0.0f;
#pragma unroll
        for (int off = 1; off < 8; off <<= 1) {
            float u = __shfl_up_sync(0xffffffffu, w, off);
            if (lane >= off) w += u;
        }
        if (lane < 8) ws[lane] = w;   // inclusive warp bases
    }
    __syncthreads();
    if (t < 256) {
        float base = (wid > 0) ? ws[wid - 1] : 0.0f;
        cs[t] = cs[t] + base;      // full inclusive scan of super-chunk sums
    }
    __syncthreads();

    // emit 100-day-chunk exclusive prefixes
    if (t < nch) {
        int c2 = t >> 1;
        float superExcl = (c2 == 0) ? 0.0f : cs[c2 - 1];
        if ((t & 1) == 0) {
            g_Pex[t] = superExcl;
        } else {
            // + first 100 days of super-chunk c2: 12 x 8-day + 4 days from r
            float h = 0.0f;
            int b = c2 * 25;
#pragma unroll
            for (int i = 0; i < 12; ++i) h += s8[b + i];
            int d = (c2 * 200) + 96;
            h += (log1p_poly(r[d] - 1.0f) + log1p_poly(r[d + 1] - 1.0f))
               + (log1p_poly(r[d + 2] - 1.0f) + log1p_poly(r[d + 3] - 1.0f));
            g_Pex[t] = superExcl + h;
        }
    }
}

// ---- main kernel: FROZEN R14 config (QS=4, two f32x2 windows, STG.128
// .cs, 4 blocks/SM, template NQ for immediate-offset stores). 37.1us.
template <int NQ>
__global__ void __launch_bounds__(128, 4) main_kernel(
    const float* __restrict__ r,      // (T,)
    const float* __restrict__ warm,   // (J,S)
    const float* __restrict__ Ts,     // (S,)
    const float* __restrict__ rho,    // (S,)
    const float* __restrict__ pi,     // (J,S)
    u64* __restrict__ out,            // (T, S/2) packed f32x2
    int T, int S)
{
    const int nquads = (NQ > 0) ? NQ : (S >> 2);
    int q = blockIdx.x * blockDim.x + threadIdx.x;   // quad index
    if (q >= nquads) {
        asm volatile("griddepcontrol.wait;" ::: "memory");
        return;
    }
    int c  = blockIdx.y;
    int d0 = c * DCH;

    float4 Ts4  = ((const float4*)Ts)[q];
    float4 rho4 = ((const float4*)rho)[q];
    float t0 = 1.0f / Ts4.x, t1 = 1.0f / Ts4.y;
    float t2 = 1.0f / Ts4.z, t3 = 1.0f / Ts4.w;

    u64 pirA[JW], pirB[JW];
#pragma unroll
    for (int j = 0; j < JW; ++j) {
        float4 p4 = ((const float4*)(pi + j * S))[q];
        pirA[j] = pk2(p4.x * rho4.x, p4.y * rho4.y);
        pirB[j] = pk2(p4.z * rho4.z, p4.w * rho4.w);
    }

    const u64 C1A = pk2(t0, t1), C1B = pk2(t2, t3);
    const u64 C2A = pk2(0.5f * t0 * (t0 - 1.0f), 0.5f * t1 * (t1 - 1.0f));
    const u64 C2B = pk2(0.5f * t2 * (t2 - 1.0f), 0.5f * t3 * (t3 - 1.0f));
    const u64 ONE2 = pk2(1.0f, 1.0f);

    u64 winA[JW], winB[JW];
    if (c == 0) {
#pragma unroll
        for (int j = 0; j < JW; ++j) {
            float4 w4 = ((const float4*)(warm + (JW - 1 - j) * S))[q];
            winA[j] = pk2(w4.x, w4.y);
            winB[j] = pk2(w4.z, w4.w);
        }
        asm volatile("griddepcontrol.wait;" ::: "memory");  // no prep data used
    } else {
        float4 wl4 = ((const float4*)(warm + (JW - 1) * S))[q];
        // --- prep-independent: window-day loads + backward multipliers ---
        // (1+v)^(-t) ~= 1 - t v + t(t+1)/2 v^2 - t(t+1)(t+2)/6 v^3
        u64 B1A = pk2(-t0, -t1), B1B = pk2(-t2, -t3);
        u64 B2A = pk2(0.5f * t0 * (t0 + 1.0f), 0.5f * t1 * (t1 + 1.0f));
        u64 B2B = pk2(0.5f * t2 * (t2 + 1.0f), 0.5f * t3 * (t3 + 1.0f));
        u64 B3A = pk2(-t0 * (t0 + 1.0f) * (t0 + 2.0f) / 6.0f,
                      -t1 * (t1 + 1.0f) * (t1 + 2.0f) / 6.0f);
        u64 B3B = pk2(-t2 * (t2 + 1.0f) * (t2 + 2.0f) / 6.0f,
                      -t3 * (t3 + 1.0f) * (t3 + 2.0f) / 6.0f);
        u64 eA[JW - 1], eB[JW - 1];
#pragma unroll
        for (int j = 1; j < JW; ++j) {
            float v = r[d0 - j] - 1.0f;
            u64 v2 = pk2(v, v);
            eA[j - 1] = fma2(v2, fma2(v2, fma2(v2, B3A, B2A), B1A), ONE2);
            eB[j - 1] = fma2(v2, fma2(v2, fma2(v2, B3B, B2B), B1B), ONE2);
        }
        // --- prep-dependent: anchor + window chain ---
        asm volatile("griddepcontrol.wait;" ::: "memory");
        float Pex = g_Pex[c];                 // sum log r[0..d0-1]
        winA[0] = pk2(wl4.x * __expf(Pex * t0), wl4.y * __expf(Pex * t1));
        winB[0] = pk2(wl4.z * __expf(Pex * t2), wl4.w * __expf(Pex * t3));
#pragma unroll
        for (int j = 1; j < JW; ++j) {
            winA[j] = mul2(winA[j - 1], eA[j - 1]);
            winB[j] = mul2(winB[j - 1], eB[j - 1]);
        }
    }
    u64 aA = winA[0], aB = winB[0];

    const float4* R4 = (const float4*)(r + d0);   // d0*4B is 400B-aligned
    u64* o = out + ((size_t)d0 * nquads + q) * 2;
    const size_t OST = (size_t)nquads * 2;        // constexpr when NQ>0

#define STEP(rv, k) do {                                            \
        u64 mA0 = mul2(pirA[0], winA[0]);                           \
        u64 mA1 = mul2(pirA[1], winA[1]);                           \
        u64 mB0 = mul2(pirB[0], winB[0]);                           \
        u64 mB1 = mul2(pirB[1], winB[1]);                           \
        mA0 = fma2(pirA[2], winA[2], mA0);                          \
        mA1 = fma2(pirA[3], winA[3], mA1);                          \
        mB0 = fma2(pirB[2], winB[2], mB0);                          \
        mB1 = fma2(pirB[3], winB[3], mB1);                          \
        mA0 = fma2(pirA[4], winA[4], mA0);                          \
        mA1 = fma2(pirA[5], winA[5], mA1);                          \
        mB0 = fma2(pirB[4], winB[4], mB0);                          \
        mB1 = fma2(pirB[5], winB[5], mB1);                          \
        mA0 = fma2(pirA[6], winA[6], mA0);                          \
        mA1 = fma2(pirA[7], winA[7], mA1);                          \
        mB0 = fma2(pirB[6], winB[6], mB0);                          \
        mB1 = fma2(pirB[7], winB[7], mB1);                          \
        mA0 = fma2(pirA[8], winA[8], mA0);                          \
        mA1 = fma2(pirA[9], winA[9], mA1);                          \
        mB0 = fma2(pirB[8], winB[8], mB0);                          \
        mB1 = fma2(pirB[9], winB[9], mB1);                          \
        stcs128(o + (size_t)(k) * OST, add2(mA0, mA1), add2(mB0, mB1)); \
        float vv = (rv) - 1.0f;                                     \
        u64 v2 = pk2(vv, vv);                                       \
        u64 eAx = fma2(v2, fma2(v2, C2A, C1A), ONE2);               \
        u64 eBx = fma2(v2, fma2(v2, C2B, C1B), ONE2);               \
        aA = mul2(aA, eAx);                                         \
        aB = mul2(aB, eBx);                                         \
        _Pragma("unroll")                                           \
        for (int j = JW - 1; j > 0; --j) {                          \
            winA[j] = winA[j - 1];                                  \
            winB[j] = winB[j - 1];                                  \
        }                                                           \
        winA[0] = aA;                                               \
        winB[0] = aB;                                               \
    } while (0)

    if (d0 + DCH <= T) {
        // 25 iters of 4 days; unroll 5 -> 20 days/body = 2 full window rotations
#pragma unroll 5
        for (int it = 0; it < DCH / 4; ++it) {
            float4 L = R4[it];
            STEP(L.x, 0);
            STEP(L.y, 1);
            STEP(L.z, 2);
            STEP(L.w, 3);
            o += 4 * OST;    // one pointer bump per 4 days (imm offsets above)
        }
    } else {
        for (int d = d0; d < T; ++d) {
            float rv = r[d];
            STEP(rv, 0);
            o += OST;
        }
    }
#undef STEP
}

extern "C" void kernel_launch(void* const* d_in, const int* in_sizes, int n_in,
                              void* d_out, int out_size) {
    const float* r    = (const float*)d_in[0];  // (1,T)
    const float* warm = (const float*)d_in[1];  // (J,S)
    const float* Ts   = (const float*)d_in[2];  // (S,)
    const float* rho  = (const float*)d_in[3];  // (S,)
    const float* pi   = (const float*)d_in[4];  // (J,S)

    int T = in_sizes[0];
    int S = in_sizes[2];
    int nch = (T + DCH - 1) / DCH;

    prep_kernel<<<1, 1024>>>(r, T, nch);

    int nquads = S / 4;
    dim3 grid((nquads + 127) / 128, nch);

    // PDL launch of main: may begin scheduling while prep runs; the
    // griddepcontrol.wait inside orders the g_Pex read after prep completes.
    cudaLaunchConfig_t cfg = {};
    cfg.gridDim = grid;
    cfg.blockDim = dim3(128, 1, 1);
    cfg.dynamicSmemBytes = 0;
    cfg.stream = 0;
    cudaLaunchAttribute at[1];
    at[0].id = cudaLaunchAttributeProgrammaticStreamSerialization;
    at[0].val.programmaticStreamSerializationAllowed = 1;
    cfg.attrs = at;
    cfg.numAttrs = 1;

    cudaError_t e;
    if (nquads == 250) {
        e = cudaLaunchKernelEx(&cfg, main_kernel<250>,
                               r, warm, Ts, rho, pi, (u64*)d_out, T, S);
        if (e != cudaSuccess)
            main_kernel<250><<<grid, 128>>>(r, warm, Ts, rho, pi,
                                            (u64*)d_out, T, S);
    } else {
        e = cudaLaunchKernelEx(&cfg, main_kernel<0>,
                               r, warm, Ts, rho, pi, (u64*)d_out, T, S);
        if (e != cudaSuccess)
            main_kernel<0><<<grid, 128>>>(r, warm, Ts, rho, pi,
                                          (u64*)d_out, T, S);
    }
}

// round 16
// speedup vs baseline: 1.1910x; 1.0296x over previous
#include <cuda_runtime.h>
#include <math.h>

#define JW 10
#define DCH 100          // days per chunk (T=50000 -> 500 chunks)
#define MAXCH 1024
#define PKMAX 13         // prep prefetch depth: covers T <= 13*4096 per block

// Scratch (allocation-free rule: __device__ globals)
__device__ float g_Pex[MAXCH];   // per-block-local exclusive log-prefixes
__device__ float g_Tot0;         // block 0's half-total (split mode)

typedef unsigned long long u64;

// ---- packed f32x2 helpers (sm_103a) ----
__device__ __forceinline__ u64 pk2(float lo, float hi) {
    u64 r; asm("mov.b64 %0, {%1, %2};" : "=l"(r) : "f"(lo), "f"(hi)); return r;
}
__device__ __forceinline__ u64 mul2(u64 a, u64 b) {
    u64 d; asm("mul.rn.f32x2 %0, %1, %2;" : "=l"(d) : "l"(a), "l"(b)); return d;
}
__device__ __forceinline__ u64 fma2(u64 a, u64 b, u64 c) {
    u64 d; asm("fma.rn.f32x2 %0, %1, %2, %3;" : "=l"(d) : "l"(a), "l"(b), "l"(c)); return d;
}
__device__ __forceinline__ u64 add2(u64 a, u64 b) {
    u64 d; asm("add.rn.f32x2 %0, %1, %2;" : "=l"(d) : "l"(a), "l"(b)); return d;
}
// 16-byte streaming store (evict-first): proven best since R8
__device__ __forceinline__ void stcs128(u64* p, u64 lo, u64 hi) {
    asm volatile("st.global.cs.v2.b64 [%0], {%1, %2};"
                 :: "l"(p), "l"(lo), "l"(hi) : "memory");
}

// log(1+x), |x| <= ~0.011: degree-4, trunc err ~2e-12/day (anchor budget ok)
__device__ __forceinline__ float log1p_poly(float x) {
    float p = fmaf(x, -0.25f, 1.0f / 3.0f);
    p = fmaf(x, p, -0.5f);
    p = fmaf(x, p, 1.0f);
    return x * p;
}

// ---- prep: 1 or 2 blocks. Block b covers chunks [b*ch0, ...) and emits
// LOCAL exclusive prefixes; block 0 additionally publishes its half-total.
// Main adds g_Tot0 for chunks >= ch0. No cross-block sync needed (PDL
// orders the whole prep grid before main's wait).
__global__ void __launch_bounds__(1024) prep_kernel(const float* __restrict__ r,
                                                    int T, int nch, int ch0) {
    // PDL: let the dependent (main) grid begin scheduling immediately.
    asm volatile("griddepcontrol.launch_dependents;" ::: "memory");

    __shared__ float s8[6272];    // 8-day log-sums (local)
    __shared__ float cs[256];     // 200-day super-chunk inclusive scan
    __shared__ float ws[8];       // per-warp scan sums
    int t = threadIdx.x;
    int lane = t & 31;
    int wid = t >> 5;
    int b = blockIdx.x;

    int chBase  = b * ch0;
    int chLocal = b ? (nch - ch0) : ((ch0 < nch) ? ch0 : nch);
    if (chLocal <= 0) return;
    int dayBase = chBase * DCH;
    long long de = (long long)(chBase + chLocal) * DCH;
    int dayEnd  = (de < (long long)T) ? (int)de : T;
    if (b && dayEnd < T && chBase + chLocal == nch) dayEnd = T;
    int nDays = dayEnd - dayBase;
    const float* rb = r + dayBase;

    int n4 = (nDays + 3) >> 2;
    int n8 = (nDays + 7) >> 3;

    // Prefetch all rounds up-front (MLP): one DRAM latency wall.
    float4 buf[PKMAX];
#pragma unroll
    for (int k = 0; k < PKMAX; ++k) {
        int i4 = k * 1024 + t;
        buf[k] = make_float4(1.0f, 1.0f, 1.0f, 1.0f);
        if (i4 * 4 + 4 <= nDays) buf[k] = *(const float4*)(rb + i4 * 4);
    }
#pragma unroll
    for (int k = 0; k < PKMAX; ++k) {
        int i4 = k * 1024 + t;
        float v = 0.0f;
        if (i4 < n4) {
            int d = i4 * 4;
            if (d + 4 <= nDays) {
                float4 rv = buf[k];
                v = (log1p_poly(rv.x - 1.0f) + log1p_poly(rv.y - 1.0f))
                  + (log1p_poly(rv.z - 1.0f) + log1p_poly(rv.w - 1.0f));
            } else {
                for (int i = d; i < nDays; ++i) v += log1p_poly(rb[i] - 1.0f);
            }
        }
        float w = v + __shfl_xor_sync(0xffffffffu, v, 1);
        int i8 = i4 >> 1;
        if ((t & 1) == 0 && i4 < n4 && i8 < n8) s8[i8] = w;
    }
    for (int k = PKMAX; k < (n4 + 1023) / 1024; ++k) {
        int i4 = k * 1024 + t;
        float v = 0.0f;
        if (i4 < n4) {
            int d = i4 * 4;
            if (d + 4 <= nDays) {
                float4 rv = *(const float4*)(rb + d);
                v = (log1p_poly(rv.x - 1.0f) + log1p_poly(rv.y - 1.0f))
                  + (log1p_poly(rv.z - 1.0f) + log1p_poly(rv.w - 1.0f));
            } else {
                for (int i = d; i < nDays; ++i) v += log1p_poly(rb[i] - 1.0f);
            }
        }
        float w = v + __shfl_xor_sync(0xffffffffu, v, 1);
        int i8 = i4 >> 1;
        if ((t & 1) == 0 && i4 < n4 && i8 < n8) s8[i8] = w;
    }
    __syncthreads();

    // 200-day super-chunk sums + shuffle-based inclusive scan (<=256 supers)
    int nsuper = (chLocal + 1) / 2;
    if (t < 256) {
        float s = 0.0f;
        if (t < nsuper) {
            int base = t * 25;     // 25 x 8-day groups per 200 days
            float a0 = 0.f, a1 = 0.f, a2 = 0.f, a3 = 0.f, a4 = 0.f;
#pragma unroll
            for (int i = 0; i < 25; i += 5) {
                a0 += s8[base + i];
                a1 += s8[base + i + 1];
                a2 += s8[base + i + 2];
                a3 += s8[base + i + 3];
                a4 += s8[base + i + 4];
            }
            s = ((a0 + a1) + (a2 + a3)) + a4;
        }
        float v = s;
#pragma unroll
        for (int off = 1; off < 32; off <<= 1) {
            float u = __shfl_up_sync(0xffffffffu, v, off);
            if (lane >= off) v += u;
        }
        if (lane == 31) ws[wid] = v;
        cs[t] = v;                 // provisional (within-warp inclusive)
    }
    __syncthreads();
    if (t < 32) {
        float w = (lane < 8) ? ws[lane] : 0.0f;
#pragma unroll
        for (int off = 1; off < 8; off <<= 1) {
            float u = __shfl_up_sync(0xffffffffu, w, off);
            if (lane >= off) w += u;
        }
        if (lane < 8) ws[lane] = w;
    }
    __syncthreads();
    if (t < 256) {
        float base = (wid > 0) ? ws[wid - 1] : 0.0f;
        float fin = cs[t] + base;  // full inclusive scan value
        cs[t] = fin;
        // block 0 publishes its half-total when running in split mode
        if (gridDim.x == 2 && b == 0 && t == nsuper - 1) g_Tot0 = fin;
    }
    __syncthreads();

    // emit (block-local) 100-day-chunk exclusive prefixes
    if (t < chLocal) {
        int lsuper = t >> 1;
        float superExcl = (lsuper == 0) ? 0.0f : cs[lsuper - 1];
        if ((t & 1) == 0) {
            g_Pex[chBase + t] = superExcl;
        } else {
            // + first 100 days of local super: 12 x 8-day + 4 days from r
            float h = 0.0f;
            int b25 = lsuper * 25;
#pragma unroll
            for (int i = 0; i < 12; ++i) h += s8[b25 + i];
            int d = lsuper * 200 + 96;
            h += (log1p_poly(rb[d] - 1.0f) + log1p_poly(rb[d + 1] - 1.0f))
               + (log1p_poly(rb[d + 2] - 1.0f) + log1p_poly(rb[d + 3] - 1.0f));
            g_Pex[chBase + t] = superExcl + h;
        }
    }
}

// ---- main kernel: FROZEN R14/R15 config (QS=4, two f32x2 windows, STG.128
// .cs, 4 blocks/SM, template NQ). Only change: + g_Tot0 for c >= ch0.
template <int NQ>
__global__ void __launch_bounds__(128, 4) main_kernel(
    const float* __restrict__ r,      // (T,)
    const float* __restrict__ warm,   // (J,S)
    const float* __restrict__ Ts,     // (S,)
    const float* __restrict__ rho,    // (S,)
    const float* __restrict__ pi,     // (J,S)
    u64* __restrict__ out,            // (T, S/2) packed f32x2
    int T, int S, int ch0)
{
    const int nquads = (NQ > 0) ? NQ : (S >> 2);
    int q = blockIdx.x * blockDim.x + threadIdx.x;   // quad index
    if (q >= nquads) {
        asm volatile("griddepcontrol.wait;" ::: "memory");
        return;
    }
    int c  = blockIdx.y;
    int d0 = c * DCH;

    float4 Ts4  = ((const float4*)Ts)[q];
    float4 rho4 = ((const float4*)rho)[q];
    float t0 = 1.0f / Ts4.x, t1 = 1.0f / Ts4.y;
    float t2 = 1.0f / Ts4.z, t3 = 1.0f / Ts4.w;

    u64 pirA[JW], pirB[JW];
#pragma unroll
    for (int j = 0; j < JW; ++j) {
        float4 p4 = ((const float4*)(pi + j * S))[q];
        pirA[j] = pk2(p4.x * rho4.x, p4.y * rho4.y);
        pirB[j] = pk2(p4.z * rho4.z, p4.w * rho4.w);
    }

    const u64 C1A = pk2(t0, t1), C1B = pk2(t2, t3);
    const u64 C2A = pk2(0.5f * t0 * (t0 - 1.0f), 0.5f * t1 * (t1 - 1.0f));
    const u64 C2B = pk2(0.5f * t2 * (t2 - 1.0f), 0.5f * t3 * (t3 - 1.0f));
    const u64 ONE2 = pk2(1.0f, 1.0f);

    u64 winA[JW], winB[JW];
    if (c == 0) {
#pragma unroll
        for (int j = 0; j < JW; ++j) {
            float4 w4 = ((const float4*)(warm + (JW - 1 - j) * S))[q];
            winA[j] = pk2(w4.x, w4.y);
            winB[j] = pk2(w4.z, w4.w);
        }
        asm volatile("griddepcontrol.wait;" ::: "memory");  // no prep data used
    } else {
        float4 wl4 = ((const float4*)(warm + (JW - 1) * S))[q];
        // --- prep-independent: window-day loads + backward multipliers ---
        u64 B1A = pk2(-t0, -t1), B1B = pk2(-t2, -t3);
        u64 B2A = pk2(0.5f * t0 * (t0 + 1.0f), 0.5f * t1 * (t1 + 1.0f));
        u64 B2B = pk2(0.5f * t2 * (t2 + 1.0f), 0.5f * t3 * (t3 + 1.0f));
        u64 B3A = pk2(-t0 * (t0 + 1.0f) * (t0 + 2.0f) / 6.0f,
                      -t1 * (t1 + 1.0f) * (t1 + 2.0f) / 6.0f);
        u64 B3B = pk2(-t2 * (t2 + 1.0f) * (t2 + 2.0f) / 6.0f,
                      -t3 * (t3 + 1.0f) * (t3 + 2.0f) / 6.0f);
        u64 eA[JW - 1], eB[JW - 1];
#pragma unroll
        for (int j = 1; j < JW; ++j) {
            float v = r[d0 - j] - 1.0f;
            u64 v2 = pk2(v, v);
            eA[j - 1] = fma2(v2, fma2(v2, fma2(v2, B3A, B2A), B1A), ONE2);
            eB[j - 1] = fma2(v2, fma2(v2, fma2(v2, B3B, B2B), B1B), ONE2);
        }
        // --- prep-dependent: anchor + window chain ---
        asm volatile("griddepcontrol.wait;" ::: "memory");
        float Pex = g_Pex[c];                 // block-local prefix
        if (c >= ch0) Pex += g_Tot0;          // add first-half total (split)
        winA[0] = pk2(wl4.x * __expf(Pex * t0), wl4.y * __expf(Pex * t1));
        winB[0] = pk2(wl4.z * __expf(Pex * t2), wl4.w * __expf(Pex * t3));
#pragma unroll
        for (int j = 1; j < JW; ++j) {
            winA[j] = mul2(winA[j - 1], eA[j - 1]);
            winB[j] = mul2(winB[j - 1], eB[j - 1]);
        }
    }
    u64 aA = winA[0], aB = winB[0];

    const float4* R4 = (const float4*)(r + d0);   // d0*4B is 400B-aligned
    u64* o = out + ((size_t)d0 * nquads + q) * 2;
    const size_t OST = (size_t)nquads * 2;        // constexpr when NQ>0

#define STEP(rv, k) do {                                            \
        u64 mA0 = mul2(pirA[0], winA[0]);                           \
        u64 mA1 = mul2(pirA[1], winA[1]);                           \
        u64 mB0 = mul2(pirB[0], winB[0]);                           \
        u64 mB1 = mul2(pirB[1], winB[1]);                           \
        mA0 = fma2(pirA[2], winA[2], mA0);                          \
        mA1 = fma2(pirA[3], winA[3], mA1);                          \
        mB0 = fma2(pirB[2], winB[2], mB0);                          \
        mB1 = fma2(pirB[3], winB[3], mB1);                          \
        mA0 = fma2(pirA[4], winA[4], mA0);                          \
        mA1 = fma2(pirA[5], winA[5], mA1);                          \
        mB0 = fma2(pirB[4], winB[4], mB0);                          \
        mB1 = fma2(pirB[5], winB[5], mB1);                          \
        mA0 = fma2(pirA[6], winA[6], mA0);                          \
        mA1 = fma2(pirA[7], winA[7], mA1);                          \
        mB0 = fma2(pirB[6], winB[6], mB0);                          \
        mB1 = fma2(pirB[7], winB[7], mB1);                          \
        mA0 = fma2(pirA[8], winA[8], mA0);                          \
        mA1 = fma2(pirA[9], winA[9], mA1);                          \
        mB0 = fma2(pirB[8], winB[8], mB0);                          \
        mB1 = fma2(pirB[9], winB[9], mB1);                          \
        stcs128(o + (size_t)(k) * OST, add2(mA0, mA1), add2(mB0, mB1)); \
        float vv = (rv) - 1.0f;                                     \
        u64 v2 = pk2(vv, vv);                                       \
        u64 eAx = fma2(v2, fma2(v2, C2A, C1A), ONE2);               \
        u64 eBx = fma2(v2, fma2(v2, C2B, C1B), ONE2);               \
        aA = mul2(aA, eAx);                                         \
        aB = mul2(aB, eBx);                                         \
        _Pragma("unroll")                                           \
        for (int j = JW - 1; j > 0; --j) {                          \
            winA[j] = winA[j - 1];                                  \
            winB[j] = winB[j - 1];                                  \
        }                                                           \
        winA[0] = aA;                                               \
        winB[0] = aB;                                               \
    } while (0)

    if (d0 + DCH <= T) {
        // 25 iters of 4 days; unroll 5 -> 20 days/body = 2 full window rotations
#pragma unroll 5
        for (int it = 0; it < DCH / 4; ++it) {
            float4 L = R4[it];
            STEP(L.x, 0);
            STEP(L.y, 1);
            STEP(L.z, 2);
            STEP(L.w, 3);
            o += 4 * OST;    // one pointer bump per 4 days (imm offsets above)
        }
    } else {
        for (int d = d0; d < T; ++d) {
            float rv = r[d];
            STEP(rv, 0);
            o += OST;
        }
    }
#undef STEP
}

extern "C" void kernel_launch(void* const* d_in, const int* in_sizes, int n_in,
                              void* d_out, int out_size) {
    const float* r    = (const float*)d_in[0];  // (1,T)
    const float* warm = (const float*)d_in[1];  // (J,S)
    const float* Ts   = (const float*)d_in[2];  // (S,)
    const float* rho  = (const float*)d_in[3];  // (S,)
    const float* pi   = (const float*)d_in[4];  // (J,S)

    int T = in_sizes[0];
    int S = in_sizes[2];
    int nch = (T + DCH - 1) / DCH;

    // Split prep across 2 blocks when halves are clean (bench: nch=500).
    bool split = (T % DCH == 0) && (nch % 2 == 0) && ((nch / 2) % 2 == 0)
                 && (nch >= 8) && (nch / 2 <= 512);
    int ch0p = split ? nch / 2 : nch;          // prep's chunk split point
    int ch0m = split ? nch / 2 : 0x7fffffff;   // main's g_Tot0 threshold

    prep_kernel<<<split ? 2 : 1, 1024>>>(r, T, nch, ch0p);

    int nquads = S / 4;
    dim3 grid((nquads + 127) / 128, nch);

    // PDL launch of main: may begin scheduling while prep runs; the
    // griddepcontrol.wait inside orders anchor reads after prep completes.
    cudaLaunchConfig_t cfg = {};
    cfg.gridDim = grid;
    cfg.blockDim = dim3(128, 1, 1);
    cfg.dynamicSmemBytes = 0;
    cfg.stream = 0;
    cudaLaunchAttribute at[1];
    at[0].id = cudaLaunchAttributeProgrammaticStreamSerialization;
    at[0].val.programmaticStreamSerializationAllowed = 1;
    cfg.attrs = at;
    cfg.numAttrs = 1;

    cudaError_t e;
    if (nquads == 250) {
        e = cudaLaunchKernelEx(&cfg, main_kernel<250>,
                               r, warm, Ts, rho, pi, (u64*)d_out, T, S, ch0m);
        if (e != cudaSuccess)
            main_kernel<250><<<grid, 128>>>(r, warm, Ts, rho, pi,
                                            (u64*)d_out, T, S, ch0m);
    } else {
        e = cudaLaunchKernelEx(&cfg, main_kernel<0>,
                               r, warm, Ts, rho, pi, (u64*)d_out, T, S, ch0m);
        if (e != cudaSuccess)
            main_kernel<0><<<grid, 128>>>(r, warm, Ts, rho, pi,
                                          (u64*)d_out, T, S, ch0m);
    }
}

// round 17
// speedup vs baseline: 1.2094x; 1.0154x over previous
#include <cuda_runtime.h>
#include <math.h>

#define JW 10
#define DCH 100          // days per chunk (T=50000 -> 500 chunks)
#define MAXCH 1024
#define PKMAX 4          // prep prefetch rounds: covers 16384 days per block
#define NBMAX 4

// Scratch (allocation-free rule: __device__ globals)
__device__ float g_Pex[MAXCH];      // per-block-local exclusive log-prefixes
__device__ float g_Tot[NBMAX];      // per-prep-block totals (blocks 0..NB-2)

typedef unsigned long long u64;

// ---- packed f32x2 helpers (sm_103a) ----
__device__ __forceinline__ u64 pk2(float lo, float hi) {
    u64 r; asm("mov.b64 %0, {%1, %2};" : "=l"(r) : "f"(lo), "f"(hi)); return r;
}
__device__ __forceinline__ u64 mul2(u64 a, u64 b) {
    u64 d; asm("mul.rn.f32x2 %0, %1, %2;" : "=l"(d) : "l"(a), "l"(b)); return d;
}
__device__ __forceinline__ u64 fma2(u64 a, u64 b, u64 c) {
    u64 d; asm("fma.rn.f32x2 %0, %1, %2, %3;" : "=l"(d) : "l"(a), "l"(b), "l"(c)); return d;
}
__device__ __forceinline__ u64 add2(u64 a, u64 b) {
    u64 d; asm("add.rn.f32x2 %0, %1, %2;" : "=l"(d) : "l"(a), "l"(b)); return d;
}
// 16-byte streaming store (evict-first): proven best since R8
__device__ __forceinline__ void stcs128(u64* p, u64 lo, u64 hi) {
    asm volatile("st.global.cs.v2.b64 [%0], {%1, %2};"
                 :: "l"(p), "l"(lo), "l"(hi) : "memory");
}

// log(1+x), |x| <= ~0.011: degree-4, trunc err ~2e-12/day (anchor budget ok)
__device__ __forceinline__ float log1p_poly(float x) {
    float p = fmaf(x, -0.25f, 1.0f / 3.0f);
    p = fmaf(x, p, -0.5f);
    p = fmaf(x, p, 1.0f);
    return x * p;
}

// ---- prep: NB blocks (1..4). Block b covers ch0 chunks (last: remainder),
// emits LOCAL exclusive prefixes; non-last blocks publish their totals.
// Main adds the region totals. No cross-block sync (PDL orders the whole
// prep grid before main's griddepcontrol.wait).
__global__ void __launch_bounds__(1024) prep_kernel(const float* __restrict__ r,
                                                    int T, int nch, int ch0) {
    // PDL: let the dependent (main) grid begin scheduling immediately.
    asm volatile("griddepcontrol.launch_dependents;" ::: "memory");

    __shared__ float s8[6272];    // 8-day log-sums (local)
    __shared__ float cs[256];     // 200-day super-chunk inclusive scan
    __shared__ float ws[8];       // per-warp scan sums
    int t = threadIdx.x;
    int lane = t & 31;
    int wid = t >> 5;
    int b = blockIdx.x;
    int NB = gridDim.x;

    int chBase  = b * ch0;
    int chLocal = (b == NB - 1) ? (nch - chBase) : ch0;
    if (chLocal <= 0) return;
    int dayBase = chBase * DCH;
    long long de = (long long)(chBase + chLocal) * DCH;
    int dayEnd  = (de < (long long)T) ? (int)de : T;
    int nDays = dayEnd - dayBase;
    const float* rb = r + dayBase;

    int n4 = (nDays + 3) >> 2;
    int n8 = (nDays + 7) >> 3;

    // Prefetch rounds up-front (MLP): one DRAM latency wall.
    float4 buf[PKMAX];
#pragma unroll
    for (int k = 0; k < PKMAX; ++k) {
        int i4 = k * 1024 + t;
        buf[k] = make_float4(1.0f, 1.0f, 1.0f, 1.0f);
        if (i4 * 4 + 4 <= nDays) buf[k] = *(const float4*)(rb + i4 * 4);
    }
#pragma unroll
    for (int k = 0; k < PKMAX; ++k) {
        int i4 = k * 1024 + t;
        float v = 0.0f;
        if (i4 < n4) {
            int d = i4 * 4;
            if (d + 4 <= nDays) {
                float4 rv = buf[k];
                v = (log1p_poly(rv.x - 1.0f) + log1p_poly(rv.y - 1.0f))
                  + (log1p_poly(rv.z - 1.0f) + log1p_poly(rv.w - 1.0f));
            } else {
                for (int i = d; i < nDays; ++i) v += log1p_poly(rb[i] - 1.0f);
            }
        }
        float w = v + __shfl_xor_sync(0xffffffffu, v, 1);
        int i8 = i4 >> 1;
        if ((t & 1) == 0 && i4 < n4 && i8 < n8) s8[i8] = w;
    }
    // fallback for days beyond prefetch reach (generic shapes only)
    for (int k = PKMAX; k < (n4 + 1023) / 1024; ++k) {
        int i4 = k * 1024 + t;
        float v = 0.0f;
        if (i4 < n4) {
            int d = i4 * 4;
            if (d + 4 <= nDays) {
                float4 rv = *(const float4*)(rb + d);
                v = (log1p_poly(rv.x - 1.0f) + log1p_poly(rv.y - 1.0f))
                  + (log1p_poly(rv.z - 1.0f) + log1p_poly(rv.w - 1.0f));
            } else {
                for (int i = d; i < nDays; ++i) v += log1p_poly(rb[i] - 1.0f);
            }
        }
        float w = v + __shfl_xor_sync(0xffffffffu, v, 1);
        int i8 = i4 >> 1;
        if ((t & 1) == 0 && i4 < n4 && i8 < n8) s8[i8] = w;
    }
    __syncthreads();

    // 200-day super-chunk sums + shuffle-based inclusive scan (<=256 supers)
    int nsuper = (chLocal + 1) / 2;
    if (t < 256) {
        float s = 0.0f;
        if (t < nsuper) {
            int base = t * 25;     // 25 x 8-day groups per 200 days
            float a0 = 0.f, a1 = 0.f, a2 = 0.f, a3 = 0.f, a4 = 0.f;
#pragma unroll
            for (int i = 0; i < 25; i += 5) {
                a0 += s8[base + i];
                a1 += s8[base + i + 1];
                a2 += s8[base + i + 2];
                a3 += s8[base + i + 3];
                a4 += s8[base + i + 4];
            }
            s = ((a0 + a1) + (a2 + a3)) + a4;
        }
        float v = s;
#pragma unroll
        for (int off = 1; off < 32; off <<= 1) {
            float u = __shfl_up_sync(0xffffffffu, v, off);
            if (lane >= off) v += u;
        }
        if (lane == 31) ws[wid] = v;
        cs[t] = v;                 // provisional (within-warp inclusive)
    }
    __syncthreads();
    if (t < 32) {
        float w = (lane < 8) ? ws[lane] : 0.0f;
#pragma unroll
        for (int off = 1; off < 8; off <<= 1) {
            float u = __shfl_up_sync(0xffffffffu, w, off);
            if (lane >= off) w += u;
        }
        if (lane < 8) ws[lane] = w;
    }
    __syncthreads();
    if (t < 256) {
        float base = (wid > 0) ? ws[wid - 1] : 0.0f;
        cs[t] = cs[t] + base;      // full inclusive scan of super-chunk sums
    }
    __syncthreads();

    // non-last blocks publish their local totals
    if (NB > 1 && b < NB - 1 && t == 0) g_Tot[b] = cs[nsuper - 1];

    // emit (block-local) 100-day-chunk exclusive prefixes
    if (t < chLocal) {
        int lsuper = t >> 1;
        float superExcl = (lsuper == 0) ? 0.0f : cs[lsuper - 1];
        if ((t & 1) == 0) {
            g_Pex[chBase + t] = superExcl;
        } else {
            // + first 100 days of local super: 12 x 8-day + 4 days from r
            float h = 0.0f;
            int b25 = lsuper * 25;
#pragma unroll
            for (int i = 0; i < 12; ++i) h += s8[b25 + i];
            int d = lsuper * 200 + 96;
            h += (log1p_poly(rb[d] - 1.0f) + log1p_poly(rb[d + 1] - 1.0f))
               + (log1p_poly(rb[d + 2] - 1.0f) + log1p_poly(rb[d + 3] - 1.0f));
            g_Pex[chBase + t] = superExcl + h;
        }
    }
}

// ---- main kernel: FROZEN R14-R16 config (QS=4, two f32x2 windows, STG.128
// .cs, 4 blocks/SM, template NQ). Anchor adds region totals (NB<=4).
template <int NQ>
__global__ void __launch_bounds__(128, 4) main_kernel(
    const float* __restrict__ r,      // (T,)
    const float* __restrict__ warm,   // (J,S)
    const float* __restrict__ Ts,     // (S,)
    const float* __restrict__ rho,    // (S,)
    const float* __restrict__ pi,     // (J,S)
    u64* __restrict__ out,            // (T, S/2) packed f32x2
    int T, int S, int ch0, int NB)
{
    const int nquads = (NQ > 0) ? NQ : (S >> 2);
    int q = blockIdx.x * blockDim.x + threadIdx.x;   // quad index
    if (q >= nquads) {
        asm volatile("griddepcontrol.wait;" ::: "memory");
        return;
    }
    int c  = blockIdx.y;
    int d0 = c * DCH;

    float4 Ts4  = ((const float4*)Ts)[q];
    float4 rho4 = ((const float4*)rho)[q];
    float t0 = 1.0f / Ts4.x, t1 = 1.0f / Ts4.y;
    float t2 = 1.0f / Ts4.z, t3 = 1.0f / Ts4.w;

    u64 pirA[JW], pirB[JW];
#pragma unroll
    for (int j = 0; j < JW; ++j) {
        float4 p4 = ((const float4*)(pi + j * S))[q];
        pirA[j] = pk2(p4.x * rho4.x, p4.y * rho4.y);
        pirB[j] = pk2(p4.z * rho4.z, p4.w * rho4.w);
    }

    const u64 C1A = pk2(t0, t1), C1B = pk2(t2, t3);
    const u64 C2A = pk2(0.5f * t0 * (t0 - 1.0f), 0.5f * t1 * (t1 - 1.0f));
    const u64 C2B = pk2(0.5f * t2 * (t2 - 1.0f), 0.5f * t3 * (t3 - 1.0f));
    const u64 ONE2 = pk2(1.0f, 1.0f);

    u64 winA[JW], winB[JW];
    if (c == 0) {
#pragma unroll
        for (int j = 0; j < JW; ++j) {
            float4 w4 = ((const float4*)(warm + (JW - 1 - j) * S))[q];
            winA[j] = pk2(w4.x, w4.y);
            winB[j] = pk2(w4.z, w4.w);
        }
        asm volatile("griddepcontrol.wait;" ::: "memory");  // no prep data used
    } else {
        float4 wl4 = ((const float4*)(warm + (JW - 1) * S))[q];
        // --- prep-independent: window-day loads + backward multipliers ---
        u64 B1A = pk2(-t0, -t1), B1B = pk2(-t2, -t3);
        u64 B2A = pk2(0.5f * t0 * (t0 + 1.0f), 0.5f * t1 * (t1 + 1.0f));
        u64 B2B = pk2(0.5f * t2 * (t2 + 1.0f), 0.5f * t3 * (t3 + 1.0f));
        u64 B3A = pk2(-t0 * (t0 + 1.0f) * (t0 + 2.0f) / 6.0f,
                      -t1 * (t1 + 1.0f) * (t1 + 2.0f) / 6.0f);
        u64 B3B = pk2(-t2 * (t2 + 1.0f) * (t2 + 2.0f) / 6.0f,
                      -t3 * (t3 + 1.0f) * (t3 + 2.0f) / 6.0f);
        u64 eA[JW - 1], eB[JW - 1];
#pragma unroll
        for (int j = 1; j < JW; ++j) {
            float v = r[d0 - j] - 1.0f;
            u64 v2 = pk2(v, v);
            eA[j - 1] = fma2(v2, fma2(v2, fma2(v2, B3A, B2A), B1A), ONE2);
            eB[j - 1] = fma2(v2, fma2(v2, fma2(v2, B3B, B2B), B1B), ONE2);
        }
        // --- prep-dependent: anchor + window chain ---
        asm volatile("griddepcontrol.wait;" ::: "memory");
        float Pex = g_Pex[c];                 // block-local prefix
        if (NB > 1) {
            int region = c / ch0;
            if (region > NB - 1) region = NB - 1;
            for (int k = 0; k < region; ++k) Pex += g_Tot[k];
        }
        winA[0] = pk2(wl4.x * __expf(Pex * t0), wl4.y * __expf(Pex * t1));
        winB[0] = pk2(wl4.z * __expf(Pex * t2), wl4.w * __expf(Pex * t3));
#pragma unroll
        for (int j = 1; j < JW; ++j) {
            winA[j] = mul2(winA[j - 1], eA[j - 1]);
            winB[j] = mul2(winB[j - 1], eB[j - 1]);
        }
    }
    u64 aA = winA[0], aB = winB[0];

    const float4* R4 = (const float4*)(r + d0);   // d0*4B is 400B-aligned
    u64* o = out + ((size_t)d0 * nquads + q) * 2;
    const size_t OST = (size_t)nquads * 2;        // constexpr when NQ>0

#define STEP(rv, k) do {                                            \
        u64 mA0 = mul2(pirA[0], winA[0]);                           \
        u64 mA1 = mul2(pirA[1], winA[1]);                           \
        u64 mB0 = mul2(pirB[0], winB[0]);                           \
        u64 mB1 = mul2(pirB[1], winB[1]);                           \
        mA0 = fma2(pirA[2], winA[2], mA0);                          \
        mA1 = fma2(pirA[3], winA[3], mA1);                          \
        mB0 = fma2(pirB[2], winB[2], mB0);                          \
        mB1 = fma2(pirB[3], winB[3], mB1);                          \
        mA0 = fma2(pirA[4], winA[4], mA0);                          \
        mA1 = fma2(pirA[5], winA[5], mA1);                          \
        mB0 = fma2(pirB[4], winB[4], mB0);                          \
        mB1 = fma2(pirB[5], winB[5], mB1);                          \
        mA0 = fma2(pirA[6], winA[6], mA0);                          \
        mA1 = fma2(pirA[7], winA[7], mA1);                          \
        mB0 = fma2(pirB[6], winB[6], mB0);                          \
        mB1 = fma2(pirB[7], winB[7], mB1);                          \
        mA0 = fma2(pirA[8], winA[8], mA0);                          \
        mA1 = fma2(pirA[9], winA[9], mA1);                          \
        mB0 = fma2(pirB[8], winB[8], mB0);                          \
        mB1 = fma2(pirB[9], winB[9], mB1);                          \
        stcs128(o + (size_t)(k) * OST, add2(mA0, mA1), add2(mB0, mB1)); \
        float vv = (rv) - 1.0f;                                     \
        u64 v2 = pk2(vv, vv);                                       \
        u64 eAx = fma2(v2, fma2(v2, C2A, C1A), ONE2);               \
        u64 eBx = fma2(v2, fma2(v2, C2B, C1B), ONE2);               \
        aA = mul2(aA, eAx);                                         \
        aB = mul2(aB, eBx);                                         \
        _Pragma("unroll")                                           \
        for (int j = JW - 1; j > 0; --j) {                          \
            winA[j] = winA[j - 1];                                  \
            winB[j] = winB[j - 1];                                  \
        }                                                           \
        winA[0] = aA;                                               \
        winB[0] = aB;                                               \
    } while (0)

    if (d0 + DCH <= T) {
        // 25 iters of 4 days; unroll 5 -> 20 days/body = 2 full window rotations
#pragma unroll 5
        for (int it = 0; it < DCH / 4; ++it) {
            float4 L = R4[it];
            STEP(L.x, 0);
            STEP(L.y, 1);
            STEP(L.z, 2);
            STEP(L.w, 3);
            o += 4 * OST;    // one pointer bump per 4 days (imm offsets above)
        }
    } else {
        for (int d = d0; d < T; ++d) {
            float rv = r[d];
            STEP(rv, 0);
            o += OST;
        }
    }
#undef STEP
}

extern "C" void kernel_launch(void* const* d_in, const int* in_sizes, int n_in,
                              void* d_out, int out_size) {
    const float* r    = (const float*)d_in[0];  // (1,T)
    const float* warm = (const float*)d_in[1];  // (J,S)
    const float* Ts   = (const float*)d_in[2];  // (S,)
    const float* rho  = (const float*)d_in[3];  // (S,)
    const float* pi   = (const float*)d_in[4];  // (J,S)

    int T = in_sizes[0];
    int S = in_sizes[2];
    int nch = (T + DCH - 1) / DCH;

    // 4-way prep split when the grain is clean (bench: nch=500 -> 124x3+128)
    int NB = 1, ch0 = 0x7fffffff;
    if ((T % 200 == 0) && (nch % 2 == 0) && nch >= 16) {
        int q4 = (nch / 4) & ~1;                    // even chunk quota
        int last = nch - 3 * q4;
        if (q4 >= 2 && last >= 2 && (last % 2 == 0) && last <= 512 && q4 <= 512) {
            NB = 4; ch0 = q4;
        } else {
            int q2 = (nch / 2) & ~1;
            int l2 = nch - q2;
            if (q2 >= 2 && l2 >= 2 && (l2 % 2 == 0) && l2 <= 512 && q2 <= 512) {
                NB = 2; ch0 = q2;
            }
        }
    }

    prep_kernel<<<NB, 1024>>>(r, T, nch, (NB > 1) ? ch0 : nch);

    int nquads = S / 4;
    dim3 grid((nquads + 127) / 128, nch);

    // PDL launch of main: may begin scheduling while prep runs; the
    // griddepcontrol.wait inside orders anchor reads after prep completes.
    cudaLaunchConfig_t cfg = {};
    cfg.gridDim = grid;
    cfg.blockDim = dim3(128, 1, 1);
    cfg.dynamicSmemBytes = 0;
    cfg.stream = 0;
    cudaLaunchAttribute at[1];
    at[0].id = cudaLaunchAttributeProgrammaticStreamSerialization;
    at[0].val.programmaticStreamSerializationAllowed = 1;
    cfg.attrs = at;
    cfg.numAttrs = 1;

    cudaError_t e;
    if (nquads == 250) {
        e = cudaLaunchKernelEx(&cfg, main_kernel<250>,
                               r, warm, Ts, rho, pi, (u64*)d_out, T, S, ch0, NB);
        if (e != cudaSuccess)
            main_kernel<250><<<grid, 128>>>(r, warm, Ts, rho, pi,
                                            (u64*)d_out, T, S, ch0, NB);
    } else {
        e = cudaLaunchKernelEx(&cfg, main_kernel<0>,
                               r, warm, Ts, rho, pi, (u64*)d_out, T, S, ch0, NB);
        if (e != cudaSuccess)
            main_kernel<0><<<grid, 128>>>(r, warm, Ts, rho, pi,
                                          (u64*)d_out, T, S, ch0, NB);
    }
}